// round 2
// baseline (speedup 1.0000x reference)
#include <cuda_runtime.h>
#include <math.h>

// Problem constants
#define D_MODEL 1024
#define S_LEN   2048
#define BATCH   2
#define HEADS   16
#define DK      64
#define DFF     4096
#define ROWS    (BATCH * S_LEN)   // 4096

// ---------------------------------------------------------------------------
// Scratch (static device globals — no runtime allocation allowed)
// ---------------------------------------------------------------------------
__device__ float g_Q [ROWS * D_MODEL];   // also reused for o-proj out / ffn2 out
__device__ float g_K [ROWS * D_MODEL];
__device__ float g_V [ROWS * D_MODEL];
__device__ float g_X1[ROWS * D_MODEL];   // after first layernorm
__device__ float g_H [ROWS * DFF];       // attn out (16MB used) then ffn hidden (64MB)

// ---------------------------------------------------------------------------
// SGEMM: C[M,N] = A[M,K] @ B[K,N] (+bias) (+relu)
// 128x128 tile, BK=16, 256 threads, 8x8 per thread, float4 everywhere.
// All dims here are multiples of 128/16 — no edge handling needed.
// ---------------------------------------------------------------------------
template <bool RELU>
__global__ __launch_bounds__(256) void sgemm128(
    const float* __restrict__ A, const float* __restrict__ B,
    const float* __restrict__ bias, float* __restrict__ C,
    int M, int N, int K)
{
    __shared__ float As[16][128];   // transposed: As[k][m]
    __shared__ float Bs[16][128];   // Bs[k][n]

    const int tid = threadIdx.x;
    const int rowBase = blockIdx.y * 128;
    const int colBase = blockIdx.x * 128;
    const int tr = tid >> 4;        // 0..15
    const int tc = tid & 15;        // 0..15

    float acc[8][8];
#pragma unroll
    for (int i = 0; i < 8; i++)
#pragma unroll
        for (int j = 0; j < 8; j++) acc[i][j] = 0.f;

    for (int k0 = 0; k0 < K; k0 += 16) {
        // Load A tile 128x16 (transposed into As)
#pragma unroll
        for (int i = 0; i < 2; i++) {
            int t  = tid * 2 + i;        // 0..511
            int r  = t >> 2;             // 0..127
            int c4 = (t & 3) * 4;        // 0,4,8,12
            float4 v = *reinterpret_cast<const float4*>(
                &A[(size_t)(rowBase + r) * K + k0 + c4]);
            As[c4 + 0][r] = v.x;
            As[c4 + 1][r] = v.y;
            As[c4 + 2][r] = v.z;
            As[c4 + 3][r] = v.w;
        }
        // Load B tile 16x128
#pragma unroll
        for (int i = 0; i < 2; i++) {
            int t  = tid * 2 + i;        // 0..511
            int r  = t >> 5;             // 0..15
            int c4 = (t & 31) * 4;       // 0..124
            float4 v = *reinterpret_cast<const float4*>(
                &B[(size_t)(k0 + r) * N + colBase + c4]);
            *reinterpret_cast<float4*>(&Bs[r][c4]) = v;
        }
        __syncthreads();

#pragma unroll
        for (int k = 0; k < 16; k++) {
            float a[8], b[8];
#pragma unroll
            for (int i = 0; i < 8; i++) a[i] = As[k][tr * 8 + i];
#pragma unroll
            for (int j = 0; j < 8; j++) b[j] = Bs[k][tc * 8 + j];
#pragma unroll
            for (int i = 0; i < 8; i++)
#pragma unroll
                for (int j = 0; j < 8; j++)
                    acc[i][j] = fmaf(a[i], b[j], acc[i][j]);
        }
        __syncthreads();
    }

    // Epilogue
#pragma unroll
    for (int i = 0; i < 8; i++) {
        int r = rowBase + tr * 8 + i;
#pragma unroll
        for (int j = 0; j < 8; j += 4) {
            int c = colBase + tc * 8 + j;
            float4 v;
            v.x = acc[i][j + 0];
            v.y = acc[i][j + 1];
            v.z = acc[i][j + 2];
            v.w = acc[i][j + 3];
            if (bias != nullptr) {
                v.x += bias[c + 0];
                v.y += bias[c + 1];
                v.z += bias[c + 2];
                v.w += bias[c + 3];
            }
            if (RELU) {
                v.x = fmaxf(v.x, 0.f);
                v.y = fmaxf(v.y, 0.f);
                v.z = fmaxf(v.z, 0.f);
                v.w = fmaxf(v.w, 0.f);
            }
            *reinterpret_cast<float4*>(&C[(size_t)r * N + c]) = v;
        }
    }
}

// ---------------------------------------------------------------------------
// Flash-attention style kernel. One block = (batch b, head h, 64-query tile).
// Streams over 64-key tiles with online softmax. fp32.
// Dynamic smem layout:
//   Qs[64][65]  (Qs[d][q], scaled by 1/8)
//   KP[64][65]  (first Ks[d][k], then reused as P[q][k])
//   Vs[64][64]  (Vs[k][d])
//   Ms[64]      (mask ints)
// ---------------------------------------------------------------------------
#define ATTN_SMEM_FLOATS (64 * 65 + 64 * 65 + 64 * 64)
#define ATTN_SMEM_BYTES  (ATTN_SMEM_FLOATS * 4 + 64 * 4)

__global__ __launch_bounds__(256) void attention_kernel(
    const float* __restrict__ Qg, const float* __restrict__ Kg,
    const float* __restrict__ Vg, const int* __restrict__ mask,
    float* __restrict__ Og)
{
    extern __shared__ float sm[];
    float* Qs = sm;                       // 64*65
    float* KP = sm + 64 * 65;             // 64*65
    float* Vs = KP + 64 * 65;             // 64*64
    int*   Ms = (int*)(Vs + 64 * 64);     // 64

    const int qt = blockIdx.x;
    const int h  = blockIdx.y;
    const int b  = blockIdx.z;
    const int tid = threadIdx.x;
    const int ty = tid >> 4;              // 0..15 -> q rows ty*4..
    const int tx = tid & 15;              // 0..15 -> cols tx*4..

    const size_t bh_off = (size_t)b * S_LEN * D_MODEL + (size_t)h * DK;
    const float* Qbase = Qg + bh_off;
    const float* Kbase = Kg + bh_off;
    const float* Vbase = Vg + bh_off;

    // Load Q tile (transposed, pre-scaled by 1/sqrt(dk)=0.125)
    for (int idx = tid; idx < 64 * 64; idx += 256) {
        int q = idx >> 6;
        int d = idx & 63;
        Qs[d * 65 + q] = Qbase[(size_t)(qt * 64 + q) * D_MODEL + d] * 0.125f;
    }

    float m[4], l[4], o[4][4];
#pragma unroll
    for (int i = 0; i < 4; i++) {
        m[i] = -1e30f;
        l[i] = 0.f;
#pragma unroll
        for (int j = 0; j < 4; j++) o[i][j] = 0.f;
    }

    for (int kt = 0; kt < S_LEN / 64; kt++) {
        // Load K (transposed) and V (natural) tiles
        for (int idx = tid; idx < 64 * 64; idx += 256) {
            int r = idx >> 6;
            int d = idx & 63;
            KP[d * 65 + r] = Kbase[(size_t)(kt * 64 + r) * D_MODEL + d];
            Vs[r * 64 + d] = Vbase[(size_t)(kt * 64 + r) * D_MODEL + d];
        }
        if (tid < 64) Ms[tid] = mask[(size_t)b * S_LEN + kt * 64 + tid];
        __syncthreads();

        // S = (Q/8) @ K^T
        float s[4][4];
#pragma unroll
        for (int i = 0; i < 4; i++)
#pragma unroll
            for (int j = 0; j < 4; j++) s[i][j] = 0.f;

        for (int d = 0; d < 64; d++) {
            float a[4], bb[4];
#pragma unroll
            for (int i = 0; i < 4; i++) a[i]  = Qs[d * 65 + ty * 4 + i];
#pragma unroll
            for (int j = 0; j < 4; j++) bb[j] = KP[d * 65 + tx * 4 + j];
#pragma unroll
            for (int i = 0; i < 4; i++)
#pragma unroll
                for (int j = 0; j < 4; j++)
                    s[i][j] = fmaf(a[i], bb[j], s[i][j]);
        }

        // Apply mask (per key column)
#pragma unroll
        for (int j = 0; j < 4; j++) {
            if (Ms[tx * 4 + j] == 0) {
#pragma unroll
                for (int i = 0; i < 4; i++) s[i][j] = -1e9f;
            }
        }

        // Row max across this tile (reduce over the 16 tx lanes)
        float tm[4];
#pragma unroll
        for (int i = 0; i < 4; i++) {
            float v = fmaxf(fmaxf(s[i][0], s[i][1]), fmaxf(s[i][2], s[i][3]));
#pragma unroll
            for (int msk = 8; msk >= 1; msk >>= 1)
                v = fmaxf(v, __shfl_xor_sync(0xffffffffu, v, msk));
            tm[i] = v;
        }

        float sc[4];
#pragma unroll
        for (int i = 0; i < 4; i++) {
            float mn = fmaxf(m[i], tm[i]);
            sc[i] = __expf(m[i] - mn);
            m[i] = mn;
        }

        // Exponentiate + tile row sums
        float ts[4];
#pragma unroll
        for (int i = 0; i < 4; i++) {
            float acc = 0.f;
#pragma unroll
            for (int j = 0; j < 4; j++) {
                float p = __expf(s[i][j] - m[i]);
                s[i][j] = p;
                acc += p;
            }
#pragma unroll
            for (int msk = 8; msk >= 1; msk >>= 1)
                acc += __shfl_xor_sync(0xffffffffu, acc, msk);
            ts[i] = acc;
        }
#pragma unroll
        for (int i = 0; i < 4; i++) {
            l[i] = l[i] * sc[i] + ts[i];
#pragma unroll
            for (int j = 0; j < 4; j++) o[i][j] *= sc[i];
        }

        // Reuse KP as P[q][k]
        __syncthreads();   // everyone done reading K data from KP
#pragma unroll
        for (int i = 0; i < 4; i++)
#pragma unroll
            for (int j = 0; j < 4; j++)
                KP[(ty * 4 + i) * 65 + tx * 4 + j] = s[i][j];
        __syncthreads();

        // O += P @ V
        for (int k = 0; k < 64; k++) {
            float a[4], bb[4];
#pragma unroll
            for (int i = 0; i < 4; i++) a[i]  = KP[(ty * 4 + i) * 65 + k];
#pragma unroll
            for (int j = 0; j < 4; j++) bb[j] = Vs[k * 64 + tx * 4 + j];
#pragma unroll
            for (int i = 0; i < 4; i++)
#pragma unroll
                for (int j = 0; j < 4; j++)
                    o[i][j] = fmaf(a[i], bb[j], o[i][j]);
        }
        __syncthreads();   // protect KP/Vs for next tile's loads
    }

    // Normalize and write: out[b, q, h*64+d]
    float* Obase = Og + bh_off;
#pragma unroll
    for (int i = 0; i < 4; i++) {
        float inv = 1.f / l[i];
#pragma unroll
        for (int j = 0; j < 4; j++) {
            Obase[(size_t)(qt * 64 + ty * 4 + i) * D_MODEL + tx * 4 + j] =
                o[i][j] * inv;
        }
    }
}

// ---------------------------------------------------------------------------
// Fused residual-add + LayerNorm (unbiased variance, matches reference:
// alpha * (v - mean) / (sqrt(var_ddof1) + eps) + beta)
// One block per row of 1024.
// ---------------------------------------------------------------------------
__global__ __launch_bounds__(256) void add_ln_kernel(
    const float* __restrict__ A, const float* __restrict__ Bp,
    const float* __restrict__ alpha, const float* __restrict__ beta,
    float* __restrict__ out)
{
    __shared__ float buf[D_MODEL];
    __shared__ float red_s[8], red_q[8];
    __shared__ float sh_mean, sh_inv;

    const int row = blockIdx.x;
    const int tid = threadIdx.x;
    const size_t base = (size_t)row * D_MODEL;

    float s = 0.f, q = 0.f;
    for (int c = tid; c < D_MODEL; c += 256) {
        float v = A[base + c] + Bp[base + c];
        buf[c] = v;
        s += v;
        q = fmaf(v, v, q);
    }
#pragma unroll
    for (int msk = 16; msk >= 1; msk >>= 1) {
        s += __shfl_xor_sync(0xffffffffu, s, msk);
        q += __shfl_xor_sync(0xffffffffu, q, msk);
    }
    if ((tid & 31) == 0) {
        red_s[tid >> 5] = s;
        red_q[tid >> 5] = q;
    }
    __syncthreads();
    if (tid == 0) {
        float S = 0.f, Q = 0.f;
#pragma unroll
        for (int i = 0; i < 8; i++) { S += red_s[i]; Q += red_q[i]; }
        float mean = S * (1.f / (float)D_MODEL);
        float var  = fmaxf((Q - (float)D_MODEL * mean * mean) *
                           (1.f / (float)(D_MODEL - 1)), 0.f);
        sh_mean = mean;
        sh_inv  = 1.f / (sqrtf(var) + 1e-6f);
    }
    __syncthreads();
    const float mean = sh_mean, inv = sh_inv;
    for (int c = tid; c < D_MODEL; c += 256)
        out[base + c] = fmaf(alpha[c], (buf[c] - mean) * inv, beta[c]);
}

// ---------------------------------------------------------------------------
// Launch
// ---------------------------------------------------------------------------
extern "C" void kernel_launch(void* const* d_in, const int* in_sizes, int n_in,
                              void* d_out, int out_size)
{
    const float* x    = (const float*)d_in[0];
    const int*   mask = (const int*)  d_in[1];
    const float* w_q  = (const float*)d_in[2];
    const float* w_k  = (const float*)d_in[3];
    const float* w_v  = (const float*)d_in[4];
    const float* w_o  = (const float*)d_in[5];
    const float* W1   = (const float*)d_in[6];
    const float* b1   = (const float*)d_in[7];
    const float* W2   = (const float*)d_in[8];
    const float* b2   = (const float*)d_in[9];
    const float* a1   = (const float*)d_in[10];
    const float* be1  = (const float*)d_in[11];
    const float* a2   = (const float*)d_in[12];
    const float* be2  = (const float*)d_in[13];
    float* out = (float*)d_out;

    float *Q, *K, *V, *X1, *H;
    cudaGetSymbolAddress((void**)&Q,  g_Q);
    cudaGetSymbolAddress((void**)&K,  g_K);
    cudaGetSymbolAddress((void**)&V,  g_V);
    cudaGetSymbolAddress((void**)&X1, g_X1);
    cudaGetSymbolAddress((void**)&H,  g_H);

    cudaFuncSetAttribute(attention_kernel,
                         cudaFuncAttributeMaxDynamicSharedMemorySize,
                         ATTN_SMEM_BYTES);

    const dim3 blk(256);
    const dim3 gProj(D_MODEL / 128, ROWS / 128);   // (8, 32)
    const dim3 gFfn1(DFF / 128, ROWS / 128);       // (32, 32)

    // QKV projections
    sgemm128<false><<<gProj, blk>>>(x, w_q, nullptr, Q, ROWS, D_MODEL, D_MODEL);
    sgemm128<false><<<gProj, blk>>>(x, w_k, nullptr, K, ROWS, D_MODEL, D_MODEL);
    sgemm128<false><<<gProj, blk>>>(x, w_v, nullptr, V, ROWS, D_MODEL, D_MODEL);

    // Attention -> H (first 16MB)
    attention_kernel<<<dim3(S_LEN / 64, HEADS, BATCH), blk, ATTN_SMEM_BYTES>>>(
        Q, K, V, mask, H);

    // Output projection -> Q (reused)
    sgemm128<false><<<gProj, blk>>>(H, w_o, nullptr, Q, ROWS, D_MODEL, D_MODEL);

    // LN1: x + attn_out -> X1
    add_ln_kernel<<<ROWS, blk>>>(x, Q, a1, be1, X1);

    // FFN
    sgemm128<true ><<<gFfn1, blk>>>(X1, W1, b1, H, ROWS, DFF, D_MODEL);
    sgemm128<false><<<gProj, blk>>>(H, W2, b2, Q, ROWS, D_MODEL, DFF);

    // LN2: X1 + ffn_out -> out
    add_ln_kernel<<<ROWS, blk>>>(X1, Q, a2, be2, out);
}

// round 3
// speedup vs baseline: 1.6393x; 1.6393x over previous
#include <cuda_runtime.h>
#include <cuda_bf16.h>
#include <math.h>
#include <stdint.h>

// Problem constants
#define D_MODEL 1024
#define S_LEN   2048
#define BATCH   2
#define HEADS   16
#define DK      64
#define DFF     4096
#define ROWS    (BATCH * S_LEN)   // 4096

#define RM (ROWS * D_MODEL)       // 4M
#define MM (D_MODEL * D_MODEL)    // 1M
#define MF (D_MODEL * DFF)        // 4M
#define RF (ROWS * DFF)           // 16M

// ---------------------------------------------------------------------------
// Scratch (static device globals — no runtime allocation allowed)
// ---------------------------------------------------------------------------
__device__ float g_Q [RM];
__device__ float g_K [RM];
__device__ float g_V [RM];
__device__ float g_X1[RM];

__device__ __nv_bfloat16 g_xh [RM], g_xl [RM];
__device__ __nv_bfloat16 g_wqh[MM], g_wql[MM];
__device__ __nv_bfloat16 g_wkh[MM], g_wkl[MM];
__device__ __nv_bfloat16 g_wvh[MM], g_wvl[MM];
__device__ __nv_bfloat16 g_woh[MM], g_wol[MM];
__device__ __nv_bfloat16 g_W1h[MF], g_W1l[MF];
__device__ __nv_bfloat16 g_W2h[MF], g_W2l[MF];
__device__ __nv_bfloat16 g_aoh[RM], g_aol[RM];
__device__ __nv_bfloat16 g_x1h[RM], g_x1l[RM];
__device__ __nv_bfloat16 g_Hh [RF], g_Hl [RF];

// ---------------------------------------------------------------------------
// Split: fp32 -> bf16 hi + bf16 lo (residual). Vectorized by 4.
// ---------------------------------------------------------------------------
__global__ __launch_bounds__(256) void split_kernel(
    const float4* __restrict__ x, __nv_bfloat16* __restrict__ hi,
    __nv_bfloat16* __restrict__ lo, int n4)
{
    int i = blockIdx.x * 256 + threadIdx.x;
    if (i >= n4) return;
    float4 v = x[i];
    __nv_bfloat16 h0 = __float2bfloat16(v.x);
    __nv_bfloat16 h1 = __float2bfloat16(v.y);
    __nv_bfloat16 h2 = __float2bfloat16(v.z);
    __nv_bfloat16 h3 = __float2bfloat16(v.w);
    __nv_bfloat162 hp0; hp0.x = h0; hp0.y = h1;
    __nv_bfloat162 hp1; hp1.x = h2; hp1.y = h3;
    *reinterpret_cast<__nv_bfloat162*>(&hi[i * 4])     = hp0;
    *reinterpret_cast<__nv_bfloat162*>(&hi[i * 4 + 2]) = hp1;
    __nv_bfloat162 lp0, lp1;
    lp0.x = __float2bfloat16(v.x - __bfloat162float(h0));
    lp0.y = __float2bfloat16(v.y - __bfloat162float(h1));
    lp1.x = __float2bfloat16(v.z - __bfloat162float(h2));
    lp1.y = __float2bfloat16(v.w - __bfloat162float(h3));
    *reinterpret_cast<__nv_bfloat162*>(&lo[i * 4])     = lp0;
    *reinterpret_cast<__nv_bfloat162*>(&lo[i * 4 + 2]) = lp1;
}

// ---------------------------------------------------------------------------
// bf16 split-3 GEMM on tensor cores (mma.sync m16n8k16).
// C[M,N] = (Ah+Al)(Bh+Bl) ~= Ah@Bh + Ah@Bl + Al@Bh   (fp32 accumulate)
// Block tile 128x128, BK=32, 256 threads (8 warps, warp tile 64x32),
// cp.async double-buffered smem, ldmatrix operand loads.
// ---------------------------------------------------------------------------
__device__ __forceinline__ void mma_16816(float* c, const uint32_t* a,
                                          const uint32_t* b)
{
    asm volatile(
        "mma.sync.aligned.m16n8k16.row.col.f32.bf16.bf16.f32 "
        "{%0,%1,%2,%3}, {%4,%5,%6,%7}, {%8,%9}, {%0,%1,%2,%3};\n"
        : "+f"(c[0]), "+f"(c[1]), "+f"(c[2]), "+f"(c[3])
        : "r"(a[0]), "r"(a[1]), "r"(a[2]), "r"(a[3]), "r"(b[0]), "r"(b[1]));
}

__device__ __forceinline__ void cp16(void* smem_dst, const void* gsrc)
{
    uint32_t d = (uint32_t)__cvta_generic_to_shared(smem_dst);
    asm volatile("cp.async.cg.shared.global [%0], [%1], 16;\n"
                 :: "r"(d), "l"(gsrc));
}

// Issue one 128x32 A tile + 32x128 B tile into buffer b.
__device__ __forceinline__ void issue_chunk(
    const __nv_bfloat16* __restrict__ Aptr,
    const __nv_bfloat16* __restrict__ Bptr,
    int k0, int tid, int rowBase, int colBase, int K, int N,
    __nv_bfloat16 (*As)[56], __nv_bfloat16 (*Bs)[136])
{
#pragma unroll
    for (int i = 0; i < 2; i++) {
        int t = tid + i * 256;
        int r = t >> 2, c8 = (t & 3) * 8;
        cp16(&As[r][c8], Aptr + (size_t)(rowBase + r) * K + k0 + c8);
    }
#pragma unroll
    for (int i = 0; i < 2; i++) {
        int t = tid + i * 256;
        int r = t >> 4, c8 = (t & 15) * 8;
        cp16(&Bs[r][c8], Bptr + (size_t)(k0 + r) * N + colBase + c8);
    }
    asm volatile("cp.async.commit_group;\n" ::: "memory");
}

template <bool BIAS, bool RELU, bool SPLIT>
__global__ __launch_bounds__(256, 2) void hgemm_split3(
    const __nv_bfloat16* __restrict__ Ah, const __nv_bfloat16* __restrict__ Al,
    const __nv_bfloat16* __restrict__ Bh, const __nv_bfloat16* __restrict__ Bl,
    const float* __restrict__ bias,
    float* __restrict__ C, __nv_bfloat16* __restrict__ Ch,
    __nv_bfloat16* __restrict__ Cl,
    int M, int N, int K)
{
    __shared__ __align__(16) __nv_bfloat16 As[2][128][56];
    __shared__ __align__(16) __nv_bfloat16 Bs[2][32][136];

    const int tid  = threadIdx.x;
    const int lane = tid & 31;
    const int warp = tid >> 5;
    const int wm   = warp & 1;        // 0..1  -> 64-row slab
    const int wn   = warp >> 1;       // 0..3  -> 32-col slab
    const int rowBase = blockIdx.y * 128;
    const int colBase = blockIdx.x * 128;

    const __nv_bfloat16* APs[3] = {Ah, Ah, Al};
    const __nv_bfloat16* BPs[3] = {Bh, Bl, Bh};
    const int cpp = K / 32;           // chunks per pass
    const int nc  = 3 * cpp;

    float acc[4][4][4];
#pragma unroll
    for (int i = 0; i < 4; i++)
#pragma unroll
        for (int j = 0; j < 4; j++)
#pragma unroll
            for (int k = 0; k < 4; k++) acc[i][j][k] = 0.f;

    issue_chunk(APs[0], BPs[0], 0, tid, rowBase, colBase, K, N, As[0], Bs[0]);

    for (int c = 0; c < nc; c++) {
        asm volatile("cp.async.wait_group 0;\n" ::: "memory");
        __syncthreads();
        const int b = c & 1;
        if (c + 1 < nc) {
            int c1 = c + 1;
            int p  = c1 / cpp;
            int k0 = (c1 - p * cpp) * 32;
            issue_chunk(APs[p], BPs[p], k0, tid, rowBase, colBase, K, N,
                        As[b ^ 1], Bs[b ^ 1]);
        }

#pragma unroll
        for (int ks = 0; ks < 32; ks += 16) {
            uint32_t afr[4][4];
#pragma unroll
            for (int fm = 0; fm < 4; fm++) {
                int row = wm * 64 + fm * 16 + (lane & 15);
                int col = ks + ((lane >> 4) << 3);
                uint32_t addr =
                    (uint32_t)__cvta_generic_to_shared(&As[b][row][col]);
                asm volatile(
                    "ldmatrix.sync.aligned.m8n8.x4.shared.b16 "
                    "{%0,%1,%2,%3}, [%4];\n"
                    : "=r"(afr[fm][0]), "=r"(afr[fm][1]),
                      "=r"(afr[fm][2]), "=r"(afr[fm][3])
                    : "r"(addr));
            }
            uint32_t bfr[4][2];
#pragma unroll
            for (int fn = 0; fn < 4; fn++) {
                int row = ks + (lane & 15);
                int col = wn * 32 + fn * 8;
                uint32_t addr =
                    (uint32_t)__cvta_generic_to_shared(&Bs[b][row][col]);
                asm volatile(
                    "ldmatrix.sync.aligned.m8n8.x2.trans.shared.b16 "
                    "{%0,%1}, [%2];\n"
                    : "=r"(bfr[fn][0]), "=r"(bfr[fn][1])
                    : "r"(addr));
            }
#pragma unroll
            for (int fm = 0; fm < 4; fm++)
#pragma unroll
                for (int fn = 0; fn < 4; fn++)
                    mma_16816(acc[fm][fn], afr[fm], bfr[fn]);
        }
        __syncthreads();
    }

    // Epilogue
#pragma unroll
    for (int fm = 0; fm < 4; fm++) {
#pragma unroll
        for (int fn = 0; fn < 4; fn++) {
            int r0 = rowBase + wm * 64 + fm * 16 + (lane >> 2);
            int c0 = colBase + wn * 32 + fn * 8 + (lane & 3) * 2;
            float bx = 0.f, by = 0.f;
            if (BIAS) { bx = bias[c0]; by = bias[c0 + 1]; }
#pragma unroll
            for (int hh = 0; hh < 2; hh++) {
                int r = r0 + hh * 8;
                float v0 = acc[fm][fn][hh * 2 + 0] + bx;
                float v1 = acc[fm][fn][hh * 2 + 1] + by;
                if (RELU) { v0 = fmaxf(v0, 0.f); v1 = fmaxf(v1, 0.f); }
                size_t idx = (size_t)r * N + c0;
                if (SPLIT) {
                    __nv_bfloat16 h0 = __float2bfloat16(v0);
                    __nv_bfloat16 h1 = __float2bfloat16(v1);
                    __nv_bfloat162 hp; hp.x = h0; hp.y = h1;
                    *reinterpret_cast<__nv_bfloat162*>(&Ch[idx]) = hp;
                    __nv_bfloat162 lp;
                    lp.x = __float2bfloat16(v0 - __bfloat162float(h0));
                    lp.y = __float2bfloat16(v1 - __bfloat162float(h1));
                    *reinterpret_cast<__nv_bfloat162*>(&Cl[idx]) = lp;
                } else {
                    *reinterpret_cast<float2*>(&C[idx]) = make_float2(v0, v1);
                }
            }
        }
    }
}

// ---------------------------------------------------------------------------
// Flash-attention style kernel (fp32, unchanged math). Epilogue writes the
// bf16 hi/lo split directly (output only feeds the O-projection GEMM).
// ---------------------------------------------------------------------------
#define ATTN_SMEM_FLOATS (64 * 65 + 64 * 65 + 64 * 64)
#define ATTN_SMEM_BYTES  (ATTN_SMEM_FLOATS * 4 + 64 * 4)

__global__ __launch_bounds__(256) void attention_kernel(
    const float* __restrict__ Qg, const float* __restrict__ Kg,
    const float* __restrict__ Vg, const int* __restrict__ mask,
    __nv_bfloat16* __restrict__ Oh, __nv_bfloat16* __restrict__ Ol)
{
    extern __shared__ float sm[];
    float* Qs = sm;                       // 64*65
    float* KP = sm + 64 * 65;             // 64*65
    float* Vs = KP + 64 * 65;             // 64*64
    int*   Ms = (int*)(Vs + 64 * 64);     // 64

    const int qt = blockIdx.x;
    const int h  = blockIdx.y;
    const int b  = blockIdx.z;
    const int tid = threadIdx.x;
    const int ty = tid >> 4;
    const int tx = tid & 15;

    const size_t bh_off = (size_t)b * S_LEN * D_MODEL + (size_t)h * DK;
    const float* Qbase = Qg + bh_off;
    const float* Kbase = Kg + bh_off;
    const float* Vbase = Vg + bh_off;

    for (int idx = tid; idx < 64 * 64; idx += 256) {
        int q = idx >> 6;
        int d = idx & 63;
        Qs[d * 65 + q] = Qbase[(size_t)(qt * 64 + q) * D_MODEL + d] * 0.125f;
    }

    float m[4], l[4], o[4][4];
#pragma unroll
    for (int i = 0; i < 4; i++) {
        m[i] = -1e30f;
        l[i] = 0.f;
#pragma unroll
        for (int j = 0; j < 4; j++) o[i][j] = 0.f;
    }

    for (int kt = 0; kt < S_LEN / 64; kt++) {
        for (int idx = tid; idx < 64 * 64; idx += 256) {
            int r = idx >> 6;
            int d = idx & 63;
            KP[d * 65 + r] = Kbase[(size_t)(kt * 64 + r) * D_MODEL + d];
            Vs[r * 64 + d] = Vbase[(size_t)(kt * 64 + r) * D_MODEL + d];
        }
        if (tid < 64) Ms[tid] = mask[(size_t)b * S_LEN + kt * 64 + tid];
        __syncthreads();

        float s[4][4];
#pragma unroll
        for (int i = 0; i < 4; i++)
#pragma unroll
            for (int j = 0; j < 4; j++) s[i][j] = 0.f;

        for (int d = 0; d < 64; d++) {
            float a[4], bb[4];
#pragma unroll
            for (int i = 0; i < 4; i++) a[i]  = Qs[d * 65 + ty * 4 + i];
#pragma unroll
            for (int j = 0; j < 4; j++) bb[j] = KP[d * 65 + tx * 4 + j];
#pragma unroll
            for (int i = 0; i < 4; i++)
#pragma unroll
                for (int j = 0; j < 4; j++)
                    s[i][j] = fmaf(a[i], bb[j], s[i][j]);
        }

#pragma unroll
        for (int j = 0; j < 4; j++) {
            if (Ms[tx * 4 + j] == 0) {
#pragma unroll
                for (int i = 0; i < 4; i++) s[i][j] = -1e9f;
            }
        }

        float tm[4];
#pragma unroll
        for (int i = 0; i < 4; i++) {
            float v = fmaxf(fmaxf(s[i][0], s[i][1]), fmaxf(s[i][2], s[i][3]));
#pragma unroll
            for (int msk = 8; msk >= 1; msk >>= 1)
                v = fmaxf(v, __shfl_xor_sync(0xffffffffu, v, msk));
            tm[i] = v;
        }

        float sc[4];
#pragma unroll
        for (int i = 0; i < 4; i++) {
            float mn = fmaxf(m[i], tm[i]);
            sc[i] = __expf(m[i] - mn);
            m[i] = mn;
        }

        float ts[4];
#pragma unroll
        for (int i = 0; i < 4; i++) {
            float accv = 0.f;
#pragma unroll
            for (int j = 0; j < 4; j++) {
                float p = __expf(s[i][j] - m[i]);
                s[i][j] = p;
                accv += p;
            }
#pragma unroll
            for (int msk = 8; msk >= 1; msk >>= 1)
                accv += __shfl_xor_sync(0xffffffffu, accv, msk);
            ts[i] = accv;
        }
#pragma unroll
        for (int i = 0; i < 4; i++) {
            l[i] = l[i] * sc[i] + ts[i];
#pragma unroll
            for (int j = 0; j < 4; j++) o[i][j] *= sc[i];
        }

        __syncthreads();
#pragma unroll
        for (int i = 0; i < 4; i++)
#pragma unroll
            for (int j = 0; j < 4; j++)
                KP[(ty * 4 + i) * 65 + tx * 4 + j] = s[i][j];
        __syncthreads();

        for (int k = 0; k < 64; k++) {
            float a[4], bb[4];
#pragma unroll
            for (int i = 0; i < 4; i++) a[i]  = KP[(ty * 4 + i) * 65 + k];
#pragma unroll
            for (int j = 0; j < 4; j++) bb[j] = Vs[k * 64 + tx * 4 + j];
#pragma unroll
            for (int i = 0; i < 4; i++)
#pragma unroll
                for (int j = 0; j < 4; j++)
                    o[i][j] = fmaf(a[i], bb[j], o[i][j]);
        }
        __syncthreads();
    }

    // Split-epilogue: write bf16 hi/lo
#pragma unroll
    for (int i = 0; i < 4; i++) {
        float inv = 1.f / l[i];
#pragma unroll
        for (int j = 0; j < 4; j++) {
            float v = o[i][j] * inv;
            size_t idx = bh_off +
                (size_t)(qt * 64 + ty * 4 + i) * D_MODEL + tx * 4 + j;
            __nv_bfloat16 hv = __float2bfloat16(v);
            Oh[idx] = hv;
            Ol[idx] = __float2bfloat16(v - __bfloat162float(hv));
        }
    }
}

// ---------------------------------------------------------------------------
// Fused residual-add + LayerNorm (unbiased variance). Optional bf16 split
// side-output for feeding the next GEMM.
// ---------------------------------------------------------------------------
template <bool SPLITOUT>
__global__ __launch_bounds__(256) void add_ln_kernel(
    const float* __restrict__ A, const float* __restrict__ Bp,
    const float* __restrict__ alpha, const float* __restrict__ beta,
    float* __restrict__ out, __nv_bfloat16* __restrict__ oh,
    __nv_bfloat16* __restrict__ ol)
{
    __shared__ float buf[D_MODEL];
    __shared__ float red_s[8], red_q[8];
    __shared__ float sh_mean, sh_inv;

    const int row = blockIdx.x;
    const int tid = threadIdx.x;
    const size_t base = (size_t)row * D_MODEL;

    float s = 0.f, q = 0.f;
    for (int c = tid; c < D_MODEL; c += 256) {
        float v = A[base + c] + Bp[base + c];
        buf[c] = v;
        s += v;
        q = fmaf(v, v, q);
    }
#pragma unroll
    for (int msk = 16; msk >= 1; msk >>= 1) {
        s += __shfl_xor_sync(0xffffffffu, s, msk);
        q += __shfl_xor_sync(0xffffffffu, q, msk);
    }
    if ((tid & 31) == 0) {
        red_s[tid >> 5] = s;
        red_q[tid >> 5] = q;
    }
    __syncthreads();
    if (tid == 0) {
        float S = 0.f, Q = 0.f;
#pragma unroll
        for (int i = 0; i < 8; i++) { S += red_s[i]; Q += red_q[i]; }
        float mean = S * (1.f / (float)D_MODEL);
        float var  = fmaxf((Q - (float)D_MODEL * mean * mean) *
                           (1.f / (float)(D_MODEL - 1)), 0.f);
        sh_mean = mean;
        sh_inv  = 1.f / (sqrtf(var) + 1e-6f);
    }
    __syncthreads();
    const float mean = sh_mean, inv = sh_inv;
    for (int c = tid; c < D_MODEL; c += 256) {
        float v = fmaf(alpha[c], (buf[c] - mean) * inv, beta[c]);
        out[base + c] = v;
        if (SPLITOUT) {
            __nv_bfloat16 hv = __float2bfloat16(v);
            oh[base + c] = hv;
            ol[base + c] = __float2bfloat16(v - __bfloat162float(hv));
        }
    }
}

// ---------------------------------------------------------------------------
// Launch
// ---------------------------------------------------------------------------
extern "C" void kernel_launch(void* const* d_in, const int* in_sizes, int n_in,
                              void* d_out, int out_size)
{
    const float* x    = (const float*)d_in[0];
    const int*   mask = (const int*)  d_in[1];
    const float* w_q  = (const float*)d_in[2];
    const float* w_k  = (const float*)d_in[3];
    const float* w_v  = (const float*)d_in[4];
    const float* w_o  = (const float*)d_in[5];
    const float* W1   = (const float*)d_in[6];
    const float* b1   = (const float*)d_in[7];
    const float* W2   = (const float*)d_in[8];
    const float* b2   = (const float*)d_in[9];
    const float* a1   = (const float*)d_in[10];
    const float* be1  = (const float*)d_in[11];
    const float* a2   = (const float*)d_in[12];
    const float* be2  = (const float*)d_in[13];
    float* out = (float*)d_out;

    float *Q, *K, *V, *X1;
    cudaGetSymbolAddress((void**)&Q,  g_Q);
    cudaGetSymbolAddress((void**)&K,  g_K);
    cudaGetSymbolAddress((void**)&V,  g_V);
    cudaGetSymbolAddress((void**)&X1, g_X1);

    __nv_bfloat16 *xh, *xl, *wqh, *wql, *wkh, *wkl, *wvh, *wvl, *woh, *wol;
    __nv_bfloat16 *W1h, *W1l, *W2h, *W2l, *aoh, *aol, *x1h, *x1l, *Hh, *Hl;
    cudaGetSymbolAddress((void**)&xh,  g_xh);  cudaGetSymbolAddress((void**)&xl,  g_xl);
    cudaGetSymbolAddress((void**)&wqh, g_wqh); cudaGetSymbolAddress((void**)&wql, g_wql);
    cudaGetSymbolAddress((void**)&wkh, g_wkh); cudaGetSymbolAddress((void**)&wkl, g_wkl);
    cudaGetSymbolAddress((void**)&wvh, g_wvh); cudaGetSymbolAddress((void**)&wvl, g_wvl);
    cudaGetSymbolAddress((void**)&woh, g_woh); cudaGetSymbolAddress((void**)&wol, g_wol);
    cudaGetSymbolAddress((void**)&W1h, g_W1h); cudaGetSymbolAddress((void**)&W1l, g_W1l);
    cudaGetSymbolAddress((void**)&W2h, g_W2h); cudaGetSymbolAddress((void**)&W2l, g_W2l);
    cudaGetSymbolAddress((void**)&aoh, g_aoh); cudaGetSymbolAddress((void**)&aol, g_aol);
    cudaGetSymbolAddress((void**)&x1h, g_x1h); cudaGetSymbolAddress((void**)&x1l, g_x1l);
    cudaGetSymbolAddress((void**)&Hh,  g_Hh);  cudaGetSymbolAddress((void**)&Hl,  g_Hl);

    cudaFuncSetAttribute(attention_kernel,
                         cudaFuncAttributeMaxDynamicSharedMemorySize,
                         ATTN_SMEM_BYTES);

    const dim3 blk(256);

    // Splits of inputs/weights
    split_kernel<<<RM / 1024, blk>>>((const float4*)x,   xh,  xl,  RM / 4);
    split_kernel<<<MM / 1024, blk>>>((const float4*)w_q, wqh, wql, MM / 4);
    split_kernel<<<MM / 1024, blk>>>((const float4*)w_k, wkh, wkl, MM / 4);
    split_kernel<<<MM / 1024, blk>>>((const float4*)w_v, wvh, wvl, MM / 4);
    split_kernel<<<MM / 1024, blk>>>((const float4*)w_o, woh, wol, MM / 4);
    split_kernel<<<MF / 1024, blk>>>((const float4*)W1,  W1h, W1l, MF / 4);
    split_kernel<<<MF / 1024, blk>>>((const float4*)W2,  W2h, W2l, MF / 4);

    const dim3 gProj(D_MODEL / 128, ROWS / 128);   // (8, 32)
    const dim3 gFfn1(DFF / 128, ROWS / 128);       // (32, 32)

    // QKV projections (tensor cores)
    hgemm_split3<false, false, false><<<gProj, blk>>>(
        xh, xl, wqh, wql, nullptr, Q, nullptr, nullptr, ROWS, D_MODEL, D_MODEL);
    hgemm_split3<false, false, false><<<gProj, blk>>>(
        xh, xl, wkh, wkl, nullptr, K, nullptr, nullptr, ROWS, D_MODEL, D_MODEL);
    hgemm_split3<false, false, false><<<gProj, blk>>>(
        xh, xl, wvh, wvl, nullptr, V, nullptr, nullptr, ROWS, D_MODEL, D_MODEL);

    // Attention (fp32) -> bf16 split output
    attention_kernel<<<dim3(S_LEN / 64, HEADS, BATCH), blk, ATTN_SMEM_BYTES>>>(
        Q, K, V, mask, aoh, aol);

    // Output projection -> Q (fp32, reused)
    hgemm_split3<false, false, false><<<gProj, blk>>>(
        aoh, aol, woh, wol, nullptr, Q, nullptr, nullptr, ROWS, D_MODEL, D_MODEL);

    // LN1: x + attn_out -> X1 (+ split)
    add_ln_kernel<true><<<ROWS, blk>>>(x, Q, a1, be1, X1, x1h, x1l);

    // FFN1: relu(X1@W1 + b1) -> bf16 split H
    hgemm_split3<true, true, true><<<gFfn1, blk>>>(
        x1h, x1l, W1h, W1l, b1, nullptr, Hh, Hl, ROWS, DFF, D_MODEL);

    // FFN2: H@W2 + b2 -> Q (fp32, reused)
    hgemm_split3<true, false, false><<<gProj, blk>>>(
        Hh, Hl, W2h, W2l, b2, Q, nullptr, nullptr, ROWS, D_MODEL, DFF);

    // LN2: X1 + ffn_out -> out
    add_ln_kernel<false><<<ROWS, blk>>>(X1, Q, a2, be2, out, nullptr, nullptr);
}

// round 5
// speedup vs baseline: 2.4065x; 1.4680x over previous
#include <cuda_runtime.h>
#include <cuda_bf16.h>
#include <math.h>
#include <stdint.h>

// Problem constants
#define D_MODEL 1024
#define S_LEN   2048
#define BATCH   2
#define HEADS   16
#define DK      64
#define DFF     4096
#define ROWS    (BATCH * S_LEN)   // 4096

#define RM (ROWS * D_MODEL)       // 4M
#define MM (D_MODEL * D_MODEL)    // 1M
#define MF (D_MODEL * DFF)        // 4M
#define RF (ROWS * DFF)           // 16M

// ---------------------------------------------------------------------------
// Scratch (static device globals — no runtime allocation allowed)
// ---------------------------------------------------------------------------
__device__ float g_O [RM];        // fp32 GEMM outputs (o-proj / ffn2)
__device__ float g_X1[RM];

__device__ __nv_bfloat16 g_Qh[RM], g_Ql[RM];
__device__ __nv_bfloat16 g_Kh[RM], g_Kl[RM];
__device__ __nv_bfloat16 g_Vh[RM], g_Vl[RM];
__device__ __nv_bfloat16 g_xh [RM], g_xl [RM];
__device__ __nv_bfloat16 g_wqh[MM], g_wql[MM];
__device__ __nv_bfloat16 g_wkh[MM], g_wkl[MM];
__device__ __nv_bfloat16 g_wvh[MM], g_wvl[MM];
__device__ __nv_bfloat16 g_woh[MM], g_wol[MM];
__device__ __nv_bfloat16 g_W1h[MF], g_W1l[MF];
__device__ __nv_bfloat16 g_W2h[MF], g_W2l[MF];
__device__ __nv_bfloat16 g_aoh[RM], g_aol[RM];
__device__ __nv_bfloat16 g_x1h[RM], g_x1l[RM];
__device__ __nv_bfloat16 g_Hh [RF], g_Hl [RF];

// ---------------------------------------------------------------------------
// Helpers
// ---------------------------------------------------------------------------
__device__ __forceinline__ uint32_t pack_bf16(float a, float b)
{
    __nv_bfloat162 t;
    t.x = __float2bfloat16(a);
    t.y = __float2bfloat16(b);
    return *reinterpret_cast<uint32_t*>(&t);
}

__device__ __forceinline__ void mma_16816(float* c, const uint32_t* a,
                                          const uint32_t* b)
{
    asm volatile(
        "mma.sync.aligned.m16n8k16.row.col.f32.bf16.bf16.f32 "
        "{%0,%1,%2,%3}, {%4,%5,%6,%7}, {%8,%9}, {%0,%1,%2,%3};\n"
        : "+f"(c[0]), "+f"(c[1]), "+f"(c[2]), "+f"(c[3])
        : "r"(a[0]), "r"(a[1]), "r"(a[2]), "r"(a[3]), "r"(b[0]), "r"(b[1]));
}

__device__ __forceinline__ void cp16(void* smem_dst, const void* gsrc)
{
    uint32_t d = (uint32_t)__cvta_generic_to_shared(smem_dst);
    asm volatile("cp.async.cg.shared.global [%0], [%1], 16;\n"
                 :: "r"(d), "l"(gsrc));
}

__device__ __forceinline__ void ldsm_x4(uint32_t* r, const void* p)
{
    uint32_t a = (uint32_t)__cvta_generic_to_shared(p);
    asm volatile("ldmatrix.sync.aligned.m8n8.x4.shared.b16 {%0,%1,%2,%3}, [%4];\n"
                 : "=r"(r[0]), "=r"(r[1]), "=r"(r[2]), "=r"(r[3]) : "r"(a));
}

__device__ __forceinline__ void ldsm_x2(uint32_t* r, const void* p)
{
    uint32_t a = (uint32_t)__cvta_generic_to_shared(p);
    asm volatile("ldmatrix.sync.aligned.m8n8.x2.shared.b16 {%0,%1}, [%2];\n"
                 : "=r"(r[0]), "=r"(r[1]) : "r"(a));
}

__device__ __forceinline__ void ldsm_x2t(uint32_t* r, const void* p)
{
    uint32_t a = (uint32_t)__cvta_generic_to_shared(p);
    asm volatile("ldmatrix.sync.aligned.m8n8.x2.trans.shared.b16 {%0,%1}, [%2];\n"
                 : "=r"(r[0]), "=r"(r[1]) : "r"(a));
}

// ---------------------------------------------------------------------------
// Split: fp32 -> bf16 hi + bf16 lo (residual). Vectorized by 4.
// ---------------------------------------------------------------------------
__global__ __launch_bounds__(256) void split_kernel(
    const float4* __restrict__ x, __nv_bfloat16* __restrict__ hi,
    __nv_bfloat16* __restrict__ lo, int n4)
{
    int i = blockIdx.x * 256 + threadIdx.x;
    if (i >= n4) return;
    float4 v = x[i];
    __nv_bfloat16 h0 = __float2bfloat16(v.x);
    __nv_bfloat16 h1 = __float2bfloat16(v.y);
    __nv_bfloat16 h2 = __float2bfloat16(v.z);
    __nv_bfloat16 h3 = __float2bfloat16(v.w);
    __nv_bfloat162 hp0; hp0.x = h0; hp0.y = h1;
    __nv_bfloat162 hp1; hp1.x = h2; hp1.y = h3;
    *reinterpret_cast<__nv_bfloat162*>(&hi[i * 4])     = hp0;
    *reinterpret_cast<__nv_bfloat162*>(&hi[i * 4 + 2]) = hp1;
    __nv_bfloat162 lp0, lp1;
    lp0.x = __float2bfloat16(v.x - __bfloat162float(h0));
    lp0.y = __float2bfloat16(v.y - __bfloat162float(h1));
    lp1.x = __float2bfloat16(v.z - __bfloat162float(h2));
    lp1.y = __float2bfloat16(v.w - __bfloat162float(h3));
    *reinterpret_cast<__nv_bfloat162*>(&lo[i * 4])     = lp0;
    *reinterpret_cast<__nv_bfloat162*>(&lo[i * 4 + 2]) = lp1;
}

// ---------------------------------------------------------------------------
// bf16 split-3 GEMM on tensor cores (mma.sync m16n8k16).
// C = Ah@Bh + Ah@Bl + Al@Bh (fp32 accumulate). 128x128x32 tiles, 8 warps.
// ---------------------------------------------------------------------------
__device__ __forceinline__ void issue_chunk(
    const __nv_bfloat16* __restrict__ Aptr,
    const __nv_bfloat16* __restrict__ Bptr,
    int k0, int tid, int rowBase, int colBase, int K, int N,
    __nv_bfloat16 (*As)[56], __nv_bfloat16 (*Bs)[136])
{
#pragma unroll
    for (int i = 0; i < 2; i++) {
        int t = tid + i * 256;
        int r = t >> 2, c8 = (t & 3) * 8;
        cp16(&As[r][c8], Aptr + (size_t)(rowBase + r) * K + k0 + c8);
    }
#pragma unroll
    for (int i = 0; i < 2; i++) {
        int t = tid + i * 256;
        int r = t >> 4, c8 = (t & 15) * 8;
        cp16(&Bs[r][c8], Bptr + (size_t)(k0 + r) * N + colBase + c8);
    }
    asm volatile("cp.async.commit_group;\n" ::: "memory");
}

template <bool BIAS, bool RELU, bool SPLIT>
__global__ __launch_bounds__(256, 2) void hgemm_split3(
    const __nv_bfloat16* __restrict__ Ah, const __nv_bfloat16* __restrict__ Al,
    const __nv_bfloat16* __restrict__ Bh, const __nv_bfloat16* __restrict__ Bl,
    const float* __restrict__ bias,
    float* __restrict__ C, __nv_bfloat16* __restrict__ Ch,
    __nv_bfloat16* __restrict__ Cl,
    int M, int N, int K)
{
    __shared__ __align__(16) __nv_bfloat16 As[2][128][56];
    __shared__ __align__(16) __nv_bfloat16 Bs[2][32][136];

    const int tid  = threadIdx.x;
    const int lane = tid & 31;
    const int warp = tid >> 5;
    const int wm   = warp & 1;
    const int wn   = warp >> 1;
    const int rowBase = blockIdx.y * 128;
    const int colBase = blockIdx.x * 128;

    const __nv_bfloat16* APs[3] = {Ah, Ah, Al};
    const __nv_bfloat16* BPs[3] = {Bh, Bl, Bh};
    const int cpp = K / 32;
    const int nc  = 3 * cpp;

    float acc[4][4][4];
#pragma unroll
    for (int i = 0; i < 4; i++)
#pragma unroll
        for (int j = 0; j < 4; j++)
#pragma unroll
            for (int k = 0; k < 4; k++) acc[i][j][k] = 0.f;

    issue_chunk(APs[0], BPs[0], 0, tid, rowBase, colBase, K, N, As[0], Bs[0]);

    for (int c = 0; c < nc; c++) {
        asm volatile("cp.async.wait_group 0;\n" ::: "memory");
        __syncthreads();
        const int b = c & 1;
        if (c + 1 < nc) {
            int c1 = c + 1;
            int p  = c1 / cpp;
            int k0 = (c1 - p * cpp) * 32;
            issue_chunk(APs[p], BPs[p], k0, tid, rowBase, colBase, K, N,
                        As[b ^ 1], Bs[b ^ 1]);
        }

#pragma unroll
        for (int ks = 0; ks < 32; ks += 16) {
            uint32_t afr[4][4];
#pragma unroll
            for (int fm = 0; fm < 4; fm++) {
                int row = wm * 64 + fm * 16 + (lane & 15);
                int col = ks + ((lane >> 4) << 3);
                ldsm_x4(afr[fm], &As[b][row][col]);
            }
            uint32_t bfr[4][2];
#pragma unroll
            for (int fn = 0; fn < 4; fn++) {
                int row = ks + (lane & 15);
                int col = wn * 32 + fn * 8;
                ldsm_x2t(bfr[fn], &Bs[b][row][col]);
            }
#pragma unroll
            for (int fm = 0; fm < 4; fm++)
#pragma unroll
                for (int fn = 0; fn < 4; fn++)
                    mma_16816(acc[fm][fn], afr[fm], bfr[fn]);
        }
        __syncthreads();
    }

#pragma unroll
    for (int fm = 0; fm < 4; fm++) {
#pragma unroll
        for (int fn = 0; fn < 4; fn++) {
            int r0 = rowBase + wm * 64 + fm * 16 + (lane >> 2);
            int c0 = colBase + wn * 32 + fn * 8 + (lane & 3) * 2;
            float bx = 0.f, by = 0.f;
            if (BIAS) { bx = bias[c0]; by = bias[c0 + 1]; }
#pragma unroll
            for (int hh = 0; hh < 2; hh++) {
                int r = r0 + hh * 8;
                float v0 = acc[fm][fn][hh * 2 + 0] + bx;
                float v1 = acc[fm][fn][hh * 2 + 1] + by;
                if (RELU) { v0 = fmaxf(v0, 0.f); v1 = fmaxf(v1, 0.f); }
                size_t idx = (size_t)r * N + c0;
                if (SPLIT) {
                    __nv_bfloat16 h0 = __float2bfloat16(v0);
                    __nv_bfloat16 h1 = __float2bfloat16(v1);
                    __nv_bfloat162 hp; hp.x = h0; hp.y = h1;
                    *reinterpret_cast<__nv_bfloat162*>(&Ch[idx]) = hp;
                    __nv_bfloat162 lp;
                    lp.x = __float2bfloat16(v0 - __bfloat162float(h0));
                    lp.y = __float2bfloat16(v1 - __bfloat162float(h1));
                    *reinterpret_cast<__nv_bfloat162*>(&Cl[idx]) = lp;
                } else {
                    *reinterpret_cast<float2*>(&C[idx]) = make_float2(v0, v1);
                }
            }
        }
    }
}

// ---------------------------------------------------------------------------
// Tensor-core flash attention. Block = (qt, h, b); 4 warps; Br=Bc=64.
// S = Qh Kh + Ql Kh + Qh Kl (fp32 acc); fp32 online softmax;
// O = Ph Vh + Pl Vh + Ph Vl  with P split in-register.
// smem tiles padded to 72 halves/row (144B, conflict-free ldmatrix).
// ---------------------------------------------------------------------------
#define APAD 72
#define ATILE (64 * APAD)                       // halves per tile
#define ATT_SMEM_BYTES (6 * ATILE * 2 + 64 * 4) // 6 tiles + mask

__global__ __launch_bounds__(128) void attn_mma(
    const __nv_bfloat16* __restrict__ Qh, const __nv_bfloat16* __restrict__ Ql,
    const __nv_bfloat16* __restrict__ Kh, const __nv_bfloat16* __restrict__ Kl,
    const __nv_bfloat16* __restrict__ Vh, const __nv_bfloat16* __restrict__ Vl,
    const int* __restrict__ mask,
    __nv_bfloat16* __restrict__ Oh, __nv_bfloat16* __restrict__ Ol)
{
    extern __shared__ __align__(16) __nv_bfloat16 smb[];
    __nv_bfloat16* sQh = smb;
    __nv_bfloat16* sQl = smb + ATILE;
    __nv_bfloat16* sKh = smb + 2 * ATILE;
    __nv_bfloat16* sKl = smb + 3 * ATILE;
    __nv_bfloat16* sVh = smb + 4 * ATILE;
    __nv_bfloat16* sVl = smb + 5 * ATILE;
    int* Ms = (int*)(smb + 6 * ATILE);

    const int qt   = blockIdx.x;
    const int h    = blockIdx.y;
    const int b    = blockIdx.z;
    const int tid  = threadIdx.x;
    const int lane = tid & 31;
    const int warp = tid >> 5;
    const int l16  = lane & 15;

    const size_t rowbase = (size_t)b * S_LEN + qt * 64;   // global row base
    const int    ch      = h * DK;                        // column base

    // Stage Q tiles (hi, lo)
    for (int i = tid; i < 512; i += 128) {
        int r = i >> 3, c8 = (i & 7) * 8;
        size_t g = (rowbase + r) * D_MODEL + ch + c8;
        cp16(&sQh[r * APAD + c8], Qh + g);
        cp16(&sQl[r * APAD + c8], Ql + g);
    }
    asm volatile("cp.async.commit_group;\n" ::: "memory");
    asm volatile("cp.async.wait_group 0;\n" ::: "memory");
    __syncthreads();

    // Q A-fragments (4 k-chunks of 16)
    uint32_t qfh[4][4], qfl[4][4];
#pragma unroll
    for (int kc = 0; kc < 4; kc++) {
        int row = warp * 16 + l16;
        int col = kc * 16 + (lane >> 4) * 8;
        ldsm_x4(qfh[kc], &sQh[row * APAD + col]);
        ldsm_x4(qfl[kc], &sQl[row * APAD + col]);
    }

    float m0 = -1e30f, m1 = -1e30f, l0 = 0.f, l1 = 0.f;
    float o[8][4];
#pragma unroll
    for (int nf = 0; nf < 8; nf++)
#pragma unroll
        for (int j = 0; j < 4; j++) o[nf][j] = 0.f;

    for (int kt = 0; kt < S_LEN / 64; kt++) {
        __syncthreads();   // previous iteration's reads complete
        for (int i = tid; i < 512; i += 128) {
            int r = i >> 3, c8 = (i & 7) * 8;
            size_t g = ((size_t)b * S_LEN + kt * 64 + r) * D_MODEL + ch + c8;
            int so = r * APAD + c8;
            cp16(&sKh[so], Kh + g);
            cp16(&sKl[so], Kl + g);
            cp16(&sVh[so], Vh + g);
            cp16(&sVl[so], Vl + g);
        }
        if (tid < 64) Ms[tid] = mask[(size_t)b * S_LEN + kt * 64 + tid];
        asm volatile("cp.async.commit_group;\n" ::: "memory");
        asm volatile("cp.async.wait_group 0;\n" ::: "memory");
        __syncthreads();

        // ---- S = Q @ K^T (3 split passes) ----
        float s[8][4];
#pragma unroll
        for (int nf = 0; nf < 8; nf++)
#pragma unroll
            for (int j = 0; j < 4; j++) s[nf][j] = 0.f;

#pragma unroll
        for (int kc = 0; kc < 4; kc++) {
            // B fragments from Ks[key][d] via non-trans ldmatrix:
            // lanes 0-7: row nf*8+lane, col kc*16 ; lanes 8-15: row nf*8+lane-8, col kc*16+8
            int rr = (l16 & 7);
            int cc = kc * 16 + (l16 >> 3) * 8;
#pragma unroll
            for (int nf = 0; nf < 8; nf++) {
                uint32_t bh[2];
                ldsm_x2(bh, &sKh[(nf * 8 + rr) * APAD + cc]);
                mma_16816(s[nf], qfh[kc], bh);
                mma_16816(s[nf], qfl[kc], bh);
            }
#pragma unroll
            for (int nf = 0; nf < 8; nf++) {
                uint32_t bl[2];
                ldsm_x2(bl, &sKl[(nf * 8 + rr) * APAD + cc]);
                mma_16816(s[nf], qfh[kc], bl);
            }
        }

        // ---- scale + mask (fp32, reference order) ----
#pragma unroll
        for (int nf = 0; nf < 8; nf++) {
            int c0 = nf * 8 + (lane & 3) * 2;
            bool z0 = (Ms[c0] == 0), z1 = (Ms[c0 + 1] == 0);
            s[nf][0] = z0 ? -1e9f : s[nf][0] * 0.125f;
            s[nf][1] = z1 ? -1e9f : s[nf][1] * 0.125f;
            s[nf][2] = z0 ? -1e9f : s[nf][2] * 0.125f;
            s[nf][3] = z1 ? -1e9f : s[nf][3] * 0.125f;
        }

        // ---- online softmax (rows r = lane>>2 and r+8) ----
        float tm0 = -1e30f, tm1 = -1e30f;
#pragma unroll
        for (int nf = 0; nf < 8; nf++) {
            tm0 = fmaxf(tm0, fmaxf(s[nf][0], s[nf][1]));
            tm1 = fmaxf(tm1, fmaxf(s[nf][2], s[nf][3]));
        }
        tm0 = fmaxf(tm0, __shfl_xor_sync(0xffffffffu, tm0, 1));
        tm0 = fmaxf(tm0, __shfl_xor_sync(0xffffffffu, tm0, 2));
        tm1 = fmaxf(tm1, __shfl_xor_sync(0xffffffffu, tm1, 1));
        tm1 = fmaxf(tm1, __shfl_xor_sync(0xffffffffu, tm1, 2));

        float mn0 = fmaxf(m0, tm0), mn1 = fmaxf(m1, tm1);
        float sc0 = __expf(m0 - mn0), sc1 = __expf(m1 - mn1);
        m0 = mn0; m1 = mn1;

        float ts0 = 0.f, ts1 = 0.f;
#pragma unroll
        for (int nf = 0; nf < 8; nf++) {
            s[nf][0] = __expf(s[nf][0] - m0);
            s[nf][1] = __expf(s[nf][1] - m0);
            s[nf][2] = __expf(s[nf][2] - m1);
            s[nf][3] = __expf(s[nf][3] - m1);
            ts0 += s[nf][0] + s[nf][1];
            ts1 += s[nf][2] + s[nf][3];
        }
        ts0 += __shfl_xor_sync(0xffffffffu, ts0, 1);
        ts0 += __shfl_xor_sync(0xffffffffu, ts0, 2);
        ts1 += __shfl_xor_sync(0xffffffffu, ts1, 1);
        ts1 += __shfl_xor_sync(0xffffffffu, ts1, 2);
        l0 = l0 * sc0 + ts0;
        l1 = l1 * sc1 + ts1;

#pragma unroll
        for (int nf = 0; nf < 8; nf++) {
            o[nf][0] *= sc0; o[nf][1] *= sc0;
            o[nf][2] *= sc1; o[nf][3] *= sc1;
        }

        // ---- O += P @ V (P split in-register; 3 passes) ----
#pragma unroll
        for (int j = 0; j < 4; j++) {      // key chunk of 16 = frags 2j, 2j+1
            uint32_t ah[4], al[4];
#pragma unroll
            for (int half = 0; half < 2; half++) {
                const float* p = s[2 * j + half];
#pragma unroll
                for (int rr2 = 0; rr2 < 2; rr2++) {
                    float p0 = p[rr2 * 2 + 0], p1 = p[rr2 * 2 + 1];
                    __nv_bfloat16 h0 = __float2bfloat16(p0);
                    __nv_bfloat16 h1 = __float2bfloat16(p1);
                    __nv_bfloat162 hp; hp.x = h0; hp.y = h1;
                    ah[half * 2 + rr2] = *reinterpret_cast<uint32_t*>(&hp);
                    al[half * 2 + rr2] =
                        pack_bf16(p0 - __bfloat162float(h0),
                                  p1 - __bfloat162float(h1));
                }
            }
            int vrow = j * 16 + l16;
#pragma unroll
            for (int nf = 0; nf < 8; nf++) {
                uint32_t bvh[2];
                ldsm_x2t(bvh, &sVh[vrow * APAD + nf * 8]);
                mma_16816(o[nf], ah, bvh);
                mma_16816(o[nf], al, bvh);
            }
#pragma unroll
            for (int nf = 0; nf < 8; nf++) {
                uint32_t bvl[2];
                ldsm_x2t(bvl, &sVl[vrow * APAD + nf * 8]);
                mma_16816(o[nf], ah, bvl);
            }
        }
    }

    // ---- normalize + split write ----
    float inv0 = 1.f / l0, inv1 = 1.f / l1;
    int r0 = warp * 16 + (lane >> 2);
#pragma unroll
    for (int nf = 0; nf < 8; nf++) {
        int c0 = ch + nf * 8 + (lane & 3) * 2;
#pragma unroll
        for (int hh = 0; hh < 2; hh++) {
            float v0 = o[nf][hh * 2 + 0] * (hh ? inv1 : inv0);
            float v1 = o[nf][hh * 2 + 1] * (hh ? inv1 : inv0);
            size_t idx = (rowbase + r0 + hh * 8) * D_MODEL + c0;
            __nv_bfloat16 h0 = __float2bfloat16(v0);
            __nv_bfloat16 h1 = __float2bfloat16(v1);
            __nv_bfloat162 hp; hp.x = h0; hp.y = h1;
            *reinterpret_cast<__nv_bfloat162*>(&Oh[idx]) = hp;
            __nv_bfloat162 lp;
            lp.x = __float2bfloat16(v0 - __bfloat162float(h0));
            lp.y = __float2bfloat16(v1 - __bfloat162float(h1));
            *reinterpret_cast<__nv_bfloat162*>(&Ol[idx]) = lp;
        }
    }
}

// ---------------------------------------------------------------------------
// Fused residual-add + LayerNorm (unbiased variance). Optional split output.
// ---------------------------------------------------------------------------
template <bool SPLITOUT>
__global__ __launch_bounds__(256) void add_ln_kernel(
    const float* __restrict__ A, const float* __restrict__ Bp,
    const float* __restrict__ alpha, const float* __restrict__ beta,
    float* __restrict__ out, __nv_bfloat16* __restrict__ oh,
    __nv_bfloat16* __restrict__ ol)
{
    __shared__ float buf[D_MODEL];
    __shared__ float red_s[8], red_q[8];
    __shared__ float sh_mean, sh_inv;

    const int row = blockIdx.x;
    const int tid = threadIdx.x;
    const size_t base = (size_t)row * D_MODEL;

    float s = 0.f, q = 0.f;
    for (int c = tid; c < D_MODEL; c += 256) {
        float v = A[base + c] + Bp[base + c];
        buf[c] = v;
        s += v;
        q = fmaf(v, v, q);
    }
#pragma unroll
    for (int msk = 16; msk >= 1; msk >>= 1) {
        s += __shfl_xor_sync(0xffffffffu, s, msk);
        q += __shfl_xor_sync(0xffffffffu, q, msk);
    }
    if ((tid & 31) == 0) {
        red_s[tid >> 5] = s;
        red_q[tid >> 5] = q;
    }
    __syncthreads();
    if (tid == 0) {
        float S = 0.f, Q = 0.f;
#pragma unroll
        for (int i = 0; i < 8; i++) { S += red_s[i]; Q += red_q[i]; }
        float mean = S * (1.f / (float)D_MODEL);
        float var  = fmaxf((Q - (float)D_MODEL * mean * mean) *
                           (1.f / (float)(D_MODEL - 1)), 0.f);
        sh_mean = mean;
        sh_inv  = 1.f / (sqrtf(var) + 1e-6f);
    }
    __syncthreads();
    const float mean = sh_mean, inv = sh_inv;
    for (int c = tid; c < D_MODEL; c += 256) {
        float v = fmaf(alpha[c], (buf[c] - mean) * inv, beta[c]);
        out[base + c] = v;
        if (SPLITOUT) {
            __nv_bfloat16 hv = __float2bfloat16(v);
            oh[base + c] = hv;
            ol[base + c] = __float2bfloat16(v - __bfloat162float(hv));
        }
    }
}

// ---------------------------------------------------------------------------
// Launch
// ---------------------------------------------------------------------------
extern "C" void kernel_launch(void* const* d_in, const int* in_sizes, int n_in,
                              void* d_out, int out_size)
{
    const float* x    = (const float*)d_in[0];
    const int*   mask = (const int*)  d_in[1];
    const float* w_q  = (const float*)d_in[2];
    const float* w_k  = (const float*)d_in[3];
    const float* w_v  = (const float*)d_in[4];
    const float* w_o  = (const float*)d_in[5];
    const float* W1   = (const float*)d_in[6];
    const float* b1   = (const float*)d_in[7];
    const float* W2   = (const float*)d_in[8];
    const float* b2   = (const float*)d_in[9];
    const float* a1   = (const float*)d_in[10];
    const float* be1  = (const float*)d_in[11];
    const float* a2   = (const float*)d_in[12];
    const float* be2  = (const float*)d_in[13];
    float* out = (float*)d_out;

    float *O, *X1;
    cudaGetSymbolAddress((void**)&O,  g_O);
    cudaGetSymbolAddress((void**)&X1, g_X1);

    __nv_bfloat16 *Qh, *Ql, *Kh, *Kl, *Vh, *Vl;
    __nv_bfloat16 *xh, *xl, *wqh, *wql, *wkh, *wkl, *wvh, *wvl, *woh, *wol;
    __nv_bfloat16 *W1h, *W1l, *W2h, *W2l, *aoh, *aol, *x1h, *x1l, *Hh, *Hl;
    cudaGetSymbolAddress((void**)&Qh,  g_Qh);  cudaGetSymbolAddress((void**)&Ql,  g_Ql);
    cudaGetSymbolAddress((void**)&Kh,  g_Kh);  cudaGetSymbolAddress((void**)&Kl,  g_Kl);
    cudaGetSymbolAddress((void**)&Vh,  g_Vh);  cudaGetSymbolAddress((void**)&Vl,  g_Vl);
    cudaGetSymbolAddress((void**)&xh,  g_xh);  cudaGetSymbolAddress((void**)&xl,  g_xl);
    cudaGetSymbolAddress((void**)&wqh, g_wqh); cudaGetSymbolAddress((void**)&wql, g_wql);
    cudaGetSymbolAddress((void**)&wkh, g_wkh); cudaGetSymbolAddress((void**)&wkl, g_wkl);
    cudaGetSymbolAddress((void**)&wvh, g_wvh); cudaGetSymbolAddress((void**)&wvl, g_wvl);
    cudaGetSymbolAddress((void**)&woh, g_woh); cudaGetSymbolAddress((void**)&wol, g_wol);
    cudaGetSymbolAddress((void**)&W1h, g_W1h); cudaGetSymbolAddress((void**)&W1l, g_W1l);
    cudaGetSymbolAddress((void**)&W2h, g_W2h); cudaGetSymbolAddress((void**)&W2l, g_W2l);
    cudaGetSymbolAddress((void**)&aoh, g_aoh); cudaGetSymbolAddress((void**)&aol, g_aol);
    cudaGetSymbolAddress((void**)&x1h, g_x1h); cudaGetSymbolAddress((void**)&x1l, g_x1l);
    cudaGetSymbolAddress((void**)&Hh,  g_Hh);  cudaGetSymbolAddress((void**)&Hl,  g_Hl);

    cudaFuncSetAttribute(attn_mma,
                         cudaFuncAttributeMaxDynamicSharedMemorySize,
                         ATT_SMEM_BYTES);

    const dim3 blk(256);

    // Splits of inputs/weights
    split_kernel<<<RM / 1024, blk>>>((const float4*)x,   xh,  xl,  RM / 4);
    split_kernel<<<MM / 1024, blk>>>((const float4*)w_q, wqh, wql, MM / 4);
    split_kernel<<<MM / 1024, blk>>>((const float4*)w_k, wkh, wkl, MM / 4);
    split_kernel<<<MM / 1024, blk>>>((const float4*)w_v, wvh, wvl, MM / 4);
    split_kernel<<<MM / 1024, blk>>>((const float4*)w_o, woh, wol, MM / 4);
    split_kernel<<<MF / 1024, blk>>>((const float4*)W1,  W1h, W1l, MF / 4);
    split_kernel<<<MF / 1024, blk>>>((const float4*)W2,  W2h, W2l, MF / 4);

    const dim3 gProj(D_MODEL / 128, ROWS / 128);   // (8, 32)
    const dim3 gFfn1(DFF / 128, ROWS / 128);       // (32, 32)

    // QKV projections -> bf16 split outputs
    hgemm_split3<false, false, true><<<gProj, blk>>>(
        xh, xl, wqh, wql, nullptr, nullptr, Qh, Ql, ROWS, D_MODEL, D_MODEL);
    hgemm_split3<false, false, true><<<gProj, blk>>>(
        xh, xl, wkh, wkl, nullptr, nullptr, Kh, Kl, ROWS, D_MODEL, D_MODEL);
    hgemm_split3<false, false, true><<<gProj, blk>>>(
        xh, xl, wvh, wvl, nullptr, nullptr, Vh, Vl, ROWS, D_MODEL, D_MODEL);

    // Tensor-core attention -> bf16 split output
    attn_mma<<<dim3(S_LEN / 64, HEADS, BATCH), dim3(128), ATT_SMEM_BYTES>>>(
        Qh, Ql, Kh, Kl, Vh, Vl, mask, aoh, aol);

    // Output projection -> fp32 O
    hgemm_split3<false, false, false><<<gProj, blk>>>(
        aoh, aol, woh, wol, nullptr, O, nullptr, nullptr, ROWS, D_MODEL, D_MODEL);

    // LN1: x + attn_out -> X1 (+ split)
    add_ln_kernel<true><<<ROWS, blk>>>(x, O, a1, be1, X1, x1h, x1l);

    // FFN1: relu(X1@W1 + b1) -> bf16 split H
    hgemm_split3<true, true, true><<<gFfn1, blk>>>(
        x1h, x1l, W1h, W1l, b1, nullptr, Hh, Hl, ROWS, DFF, D_MODEL);

    // FFN2: H@W2 + b2 -> fp32 O
    hgemm_split3<true, false, false><<<gProj, blk>>>(
        Hh, Hl, W2h, W2l, b2, O, nullptr, nullptr, ROWS, D_MODEL, DFF);

    // LN2: X1 + ffn_out -> out
    add_ln_kernel<false><<<ROWS, blk>>>(X1, O, a2, be2, out, nullptr, nullptr);
}

// round 6
// speedup vs baseline: 2.4096x; 1.0013x over previous
#include <cuda_runtime.h>
#include <cuda_bf16.h>
#include <math.h>
#include <stdint.h>

// Problem constants
#define D_MODEL 1024
#define S_LEN   2048
#define BATCH   2
#define HEADS   16
#define DK      64
#define DFF     4096
#define ROWS    (BATCH * S_LEN)   // 4096

#define RM (ROWS * D_MODEL)       // 4M
#define MM (D_MODEL * D_MODEL)    // 1M
#define MF (D_MODEL * DFF)        // 4M
#define RF (ROWS * DFF)           // 16M

// ---------------------------------------------------------------------------
// Scratch (static device globals — no runtime allocation allowed)
// ---------------------------------------------------------------------------
__device__ float g_O [RM];        // fp32 GEMM outputs (o-proj / ffn2)
__device__ float g_X1[RM];

__device__ __nv_bfloat16 g_Qh[RM], g_Ql[RM];
__device__ __nv_bfloat16 g_Kh[RM], g_Kl[RM];
__device__ __nv_bfloat16 g_Vh[RM], g_Vl[RM];
__device__ __nv_bfloat16 g_xh [RM], g_xl [RM];
__device__ __nv_bfloat16 g_wqh[MM], g_wql[MM];
__device__ __nv_bfloat16 g_wkh[MM], g_wkl[MM];
__device__ __nv_bfloat16 g_wvh[MM], g_wvl[MM];
__device__ __nv_bfloat16 g_woh[MM], g_wol[MM];
__device__ __nv_bfloat16 g_W1h[MF], g_W1l[MF];
__device__ __nv_bfloat16 g_W2h[MF], g_W2l[MF];
__device__ __nv_bfloat16 g_aoh[RM], g_aol[RM];
__device__ __nv_bfloat16 g_x1h[RM], g_x1l[RM];
__device__ __nv_bfloat16 g_Hh [RF], g_Hl [RF];

// ---------------------------------------------------------------------------
// Helpers
// ---------------------------------------------------------------------------
__device__ __forceinline__ uint32_t pack_bf16(float a, float b)
{
    __nv_bfloat162 t;
    t.x = __float2bfloat16(a);
    t.y = __float2bfloat16(b);
    return *reinterpret_cast<uint32_t*>(&t);
}

__device__ __forceinline__ void mma_16816(float* c, const uint32_t* a,
                                          const uint32_t* b)
{
    asm volatile(
        "mma.sync.aligned.m16n8k16.row.col.f32.bf16.bf16.f32 "
        "{%0,%1,%2,%3}, {%4,%5,%6,%7}, {%8,%9}, {%0,%1,%2,%3};\n"
        : "+f"(c[0]), "+f"(c[1]), "+f"(c[2]), "+f"(c[3])
        : "r"(a[0]), "r"(a[1]), "r"(a[2]), "r"(a[3]), "r"(b[0]), "r"(b[1]));
}

__device__ __forceinline__ void cp16(void* smem_dst, const void* gsrc)
{
    uint32_t d = (uint32_t)__cvta_generic_to_shared(smem_dst);
    asm volatile("cp.async.cg.shared.global [%0], [%1], 16;\n"
                 :: "r"(d), "l"(gsrc));
}

__device__ __forceinline__ void ldsm_x4(uint32_t* r, const void* p)
{
    uint32_t a = (uint32_t)__cvta_generic_to_shared(p);
    asm volatile("ldmatrix.sync.aligned.m8n8.x4.shared.b16 {%0,%1,%2,%3}, [%4];\n"
                 : "=r"(r[0]), "=r"(r[1]), "=r"(r[2]), "=r"(r[3]) : "r"(a));
}

__device__ __forceinline__ void ldsm_x2(uint32_t* r, const void* p)
{
    uint32_t a = (uint32_t)__cvta_generic_to_shared(p);
    asm volatile("ldmatrix.sync.aligned.m8n8.x2.shared.b16 {%0,%1}, [%2];\n"
                 : "=r"(r[0]), "=r"(r[1]) : "r"(a));
}

__device__ __forceinline__ void ldsm_x2t(uint32_t* r, const void* p)
{
    uint32_t a = (uint32_t)__cvta_generic_to_shared(p);
    asm volatile("ldmatrix.sync.aligned.m8n8.x2.trans.shared.b16 {%0,%1}, [%2];\n"
                 : "=r"(r[0]), "=r"(r[1]) : "r"(a));
}

// ---------------------------------------------------------------------------
// Split: fp32 -> bf16 hi + bf16 lo (residual). Vectorized by 4.
// ---------------------------------------------------------------------------
__global__ __launch_bounds__(256) void split_kernel(
    const float4* __restrict__ x, __nv_bfloat16* __restrict__ hi,
    __nv_bfloat16* __restrict__ lo, int n4)
{
    int i = blockIdx.x * 256 + threadIdx.x;
    if (i >= n4) return;
    float4 v = x[i];
    __nv_bfloat16 h0 = __float2bfloat16(v.x);
    __nv_bfloat16 h1 = __float2bfloat16(v.y);
    __nv_bfloat16 h2 = __float2bfloat16(v.z);
    __nv_bfloat16 h3 = __float2bfloat16(v.w);
    __nv_bfloat162 hp0; hp0.x = h0; hp0.y = h1;
    __nv_bfloat162 hp1; hp1.x = h2; hp1.y = h3;
    *reinterpret_cast<__nv_bfloat162*>(&hi[i * 4])     = hp0;
    *reinterpret_cast<__nv_bfloat162*>(&hi[i * 4 + 2]) = hp1;
    __nv_bfloat162 lp0, lp1;
    lp0.x = __float2bfloat16(v.x - __bfloat162float(h0));
    lp0.y = __float2bfloat16(v.y - __bfloat162float(h1));
    lp1.x = __float2bfloat16(v.z - __bfloat162float(h2));
    lp1.y = __float2bfloat16(v.w - __bfloat162float(h3));
    *reinterpret_cast<__nv_bfloat162*>(&lo[i * 4])     = lp0;
    *reinterpret_cast<__nv_bfloat162*>(&lo[i * 4 + 2]) = lp1;
}

// ---------------------------------------------------------------------------
// bf16 split-3 GEMM on tensor cores (mma.sync m16n8k16).
// C = Ah@Bh + Ah@Bl + Al@Bh (fp32 accumulate). 128x128x32 tiles, 8 warps.
// ---------------------------------------------------------------------------
__device__ __forceinline__ void issue_chunk(
    const __nv_bfloat16* __restrict__ Aptr,
    const __nv_bfloat16* __restrict__ Bptr,
    int k0, int tid, int rowBase, int colBase, int K, int N,
    __nv_bfloat16 (*As)[56], __nv_bfloat16 (*Bs)[136])
{
#pragma unroll
    for (int i = 0; i < 2; i++) {
        int t = tid + i * 256;
        int r = t >> 2, c8 = (t & 3) * 8;
        cp16(&As[r][c8], Aptr + (size_t)(rowBase + r) * K + k0 + c8);
    }
#pragma unroll
    for (int i = 0; i < 2; i++) {
        int t = tid + i * 256;
        int r = t >> 4, c8 = (t & 15) * 8;
        cp16(&Bs[r][c8], Bptr + (size_t)(k0 + r) * N + colBase + c8);
    }
    asm volatile("cp.async.commit_group;\n" ::: "memory");
}

template <bool BIAS, bool RELU, bool SPLIT>
__global__ __launch_bounds__(256, 2) void hgemm_split3(
    const __nv_bfloat16* __restrict__ Ah, const __nv_bfloat16* __restrict__ Al,
    const __nv_bfloat16* __restrict__ Bh, const __nv_bfloat16* __restrict__ Bl,
    const float* __restrict__ bias,
    float* __restrict__ C, __nv_bfloat16* __restrict__ Ch,
    __nv_bfloat16* __restrict__ Cl,
    int M, int N, int K)
{
    __shared__ __align__(16) __nv_bfloat16 As[2][128][56];
    __shared__ __align__(16) __nv_bfloat16 Bs[2][32][136];

    const int tid  = threadIdx.x;
    const int lane = tid & 31;
    const int warp = tid >> 5;
    const int wm   = warp & 1;
    const int wn   = warp >> 1;
    const int rowBase = blockIdx.y * 128;
    const int colBase = blockIdx.x * 128;

    const __nv_bfloat16* APs[3] = {Ah, Ah, Al};
    const __nv_bfloat16* BPs[3] = {Bh, Bl, Bh};
    const int cpp = K / 32;
    const int nc  = 3 * cpp;

    float acc[4][4][4];
#pragma unroll
    for (int i = 0; i < 4; i++)
#pragma unroll
        for (int j = 0; j < 4; j++)
#pragma unroll
            for (int k = 0; k < 4; k++) acc[i][j][k] = 0.f;

    issue_chunk(APs[0], BPs[0], 0, tid, rowBase, colBase, K, N, As[0], Bs[0]);

    for (int c = 0; c < nc; c++) {
        asm volatile("cp.async.wait_group 0;\n" ::: "memory");
        __syncthreads();
        const int b = c & 1;
        if (c + 1 < nc) {
            int c1 = c + 1;
            int p  = c1 / cpp;
            int k0 = (c1 - p * cpp) * 32;
            issue_chunk(APs[p], BPs[p], k0, tid, rowBase, colBase, K, N,
                        As[b ^ 1], Bs[b ^ 1]);
        }

#pragma unroll
        for (int ks = 0; ks < 32; ks += 16) {
            uint32_t afr[4][4];
#pragma unroll
            for (int fm = 0; fm < 4; fm++) {
                int row = wm * 64 + fm * 16 + (lane & 15);
                int col = ks + ((lane >> 4) << 3);
                ldsm_x4(afr[fm], &As[b][row][col]);
            }
            uint32_t bfr[4][2];
#pragma unroll
            for (int fn = 0; fn < 4; fn++) {
                int row = ks + (lane & 15);
                int col = wn * 32 + fn * 8;
                ldsm_x2t(bfr[fn], &Bs[b][row][col]);
            }
#pragma unroll
            for (int fm = 0; fm < 4; fm++)
#pragma unroll
                for (int fn = 0; fn < 4; fn++)
                    mma_16816(acc[fm][fn], afr[fm], bfr[fn]);
        }
        __syncthreads();
    }

#pragma unroll
    for (int fm = 0; fm < 4; fm++) {
#pragma unroll
        for (int fn = 0; fn < 4; fn++) {
            int r0 = rowBase + wm * 64 + fm * 16 + (lane >> 2);
            int c0 = colBase + wn * 32 + fn * 8 + (lane & 3) * 2;
            float bx = 0.f, by = 0.f;
            if (BIAS) { bx = bias[c0]; by = bias[c0 + 1]; }
#pragma unroll
            for (int hh = 0; hh < 2; hh++) {
                int r = r0 + hh * 8;
                float v0 = acc[fm][fn][hh * 2 + 0] + bx;
                float v1 = acc[fm][fn][hh * 2 + 1] + by;
                if (RELU) { v0 = fmaxf(v0, 0.f); v1 = fmaxf(v1, 0.f); }
                size_t idx = (size_t)r * N + c0;
                if (SPLIT) {
                    __nv_bfloat16 h0 = __float2bfloat16(v0);
                    __nv_bfloat16 h1 = __float2bfloat16(v1);
                    __nv_bfloat162 hp; hp.x = h0; hp.y = h1;
                    *reinterpret_cast<__nv_bfloat162*>(&Ch[idx]) = hp;
                    __nv_bfloat162 lp;
                    lp.x = __float2bfloat16(v0 - __bfloat162float(h0));
                    lp.y = __float2bfloat16(v1 - __bfloat162float(h1));
                    *reinterpret_cast<__nv_bfloat162*>(&Cl[idx]) = lp;
                } else {
                    *reinterpret_cast<float2*>(&C[idx]) = make_float2(v0, v1);
                }
            }
        }
    }
}

// ---------------------------------------------------------------------------
// Tensor-core flash attention. Block = (qt, h, b); 4 warps; Br=Bc=64.
// S = Qh Kh + Ql Kh + Qh Kl (fp32 acc); fp32 online softmax;
// O = Ph Vh + Pl Vh + Ph Vl  with P split in-register.
// smem tiles padded to 72 halves/row (144B, conflict-free ldmatrix).
// ---------------------------------------------------------------------------
#define APAD 72
#define ATILE (64 * APAD)                       // halves per tile
#define ATT_SMEM_BYTES (6 * ATILE * 2 + 64 * 4) // 6 tiles + mask

__global__ __launch_bounds__(128) void attn_mma(
    const __nv_bfloat16* __restrict__ Qh, const __nv_bfloat16* __restrict__ Ql,
    const __nv_bfloat16* __restrict__ Kh, const __nv_bfloat16* __restrict__ Kl,
    const __nv_bfloat16* __restrict__ Vh, const __nv_bfloat16* __restrict__ Vl,
    const int* __restrict__ mask,
    __nv_bfloat16* __restrict__ Oh, __nv_bfloat16* __restrict__ Ol)
{
    extern __shared__ __align__(16) __nv_bfloat16 smb[];
    __nv_bfloat16* sQh = smb;
    __nv_bfloat16* sQl = smb + ATILE;
    __nv_bfloat16* sKh = smb + 2 * ATILE;
    __nv_bfloat16* sKl = smb + 3 * ATILE;
    __nv_bfloat16* sVh = smb + 4 * ATILE;
    __nv_bfloat16* sVl = smb + 5 * ATILE;
    int* Ms = (int*)(smb + 6 * ATILE);

    const int qt   = blockIdx.x;
    const int h    = blockIdx.y;
    const int b    = blockIdx.z;
    const int tid  = threadIdx.x;
    const int lane = tid & 31;
    const int warp = tid >> 5;
    const int l16  = lane & 15;

    const size_t rowbase = (size_t)b * S_LEN + qt * 64;   // global row base
    const int    ch      = h * DK;                        // column base

    // Stage Q tiles (hi, lo)
    for (int i = tid; i < 512; i += 128) {
        int r = i >> 3, c8 = (i & 7) * 8;
        size_t g = (rowbase + r) * D_MODEL + ch + c8;
        cp16(&sQh[r * APAD + c8], Qh + g);
        cp16(&sQl[r * APAD + c8], Ql + g);
    }
    asm volatile("cp.async.commit_group;\n" ::: "memory");
    asm volatile("cp.async.wait_group 0;\n" ::: "memory");
    __syncthreads();

    // Q A-fragments (4 k-chunks of 16)
    uint32_t qfh[4][4], qfl[4][4];
#pragma unroll
    for (int kc = 0; kc < 4; kc++) {
        int row = warp * 16 + l16;
        int col = kc * 16 + (lane >> 4) * 8;
        ldsm_x4(qfh[kc], &sQh[row * APAD + col]);
        ldsm_x4(qfl[kc], &sQl[row * APAD + col]);
    }

    float m0 = -1e30f, m1 = -1e30f, l0 = 0.f, l1 = 0.f;
    float o[8][4];
#pragma unroll
    for (int nf = 0; nf < 8; nf++)
#pragma unroll
        for (int j = 0; j < 4; j++) o[nf][j] = 0.f;

    for (int kt = 0; kt < S_LEN / 64; kt++) {
        __syncthreads();   // previous iteration's reads complete
        for (int i = tid; i < 512; i += 128) {
            int r = i >> 3, c8 = (i & 7) * 8;
            size_t g = ((size_t)b * S_LEN + kt * 64 + r) * D_MODEL + ch + c8;
            int so = r * APAD + c8;
            cp16(&sKh[so], Kh + g);
            cp16(&sKl[so], Kl + g);
            cp16(&sVh[so], Vh + g);
            cp16(&sVl[so], Vl + g);
        }
        if (tid < 64) Ms[tid] = mask[(size_t)b * S_LEN + kt * 64 + tid];
        asm volatile("cp.async.commit_group;\n" ::: "memory");
        asm volatile("cp.async.wait_group 0;\n" ::: "memory");
        __syncthreads();

        // ---- S = Q @ K^T (3 split passes) ----
        float s[8][4];
#pragma unroll
        for (int nf = 0; nf < 8; nf++)
#pragma unroll
            for (int j = 0; j < 4; j++) s[nf][j] = 0.f;

#pragma unroll
        for (int kc = 0; kc < 4; kc++) {
            // B fragments from Ks[key][d] via non-trans ldmatrix:
            // lanes 0-7: row nf*8+lane, col kc*16 ; lanes 8-15: row nf*8+lane-8, col kc*16+8
            int rr = (l16 & 7);
            int cc = kc * 16 + (l16 >> 3) * 8;
#pragma unroll
            for (int nf = 0; nf < 8; nf++) {
                uint32_t bh[2];
                ldsm_x2(bh, &sKh[(nf * 8 + rr) * APAD + cc]);
                mma_16816(s[nf], qfh[kc], bh);
                mma_16816(s[nf], qfl[kc], bh);
            }
#pragma unroll
            for (int nf = 0; nf < 8; nf++) {
                uint32_t bl[2];
                ldsm_x2(bl, &sKl[(nf * 8 + rr) * APAD + cc]);
                mma_16816(s[nf], qfh[kc], bl);
            }
        }

        // ---- scale + mask (fp32, reference order) ----
#pragma unroll
        for (int nf = 0; nf < 8; nf++) {
            int c0 = nf * 8 + (lane & 3) * 2;
            bool z0 = (Ms[c0] == 0), z1 = (Ms[c0 + 1] == 0);
            s[nf][0] = z0 ? -1e9f : s[nf][0] * 0.125f;
            s[nf][1] = z1 ? -1e9f : s[nf][1] * 0.125f;
            s[nf][2] = z0 ? -1e9f : s[nf][2] * 0.125f;
            s[nf][3] = z1 ? -1e9f : s[nf][3] * 0.125f;
        }

        // ---- online softmax (rows r = lane>>2 and r+8) ----
        float tm0 = -1e30f, tm1 = -1e30f;
#pragma unroll
        for (int nf = 0; nf < 8; nf++) {
            tm0 = fmaxf(tm0, fmaxf(s[nf][0], s[nf][1]));
            tm1 = fmaxf(tm1, fmaxf(s[nf][2], s[nf][3]));
        }
        tm0 = fmaxf(tm0, __shfl_xor_sync(0xffffffffu, tm0, 1));
        tm0 = fmaxf(tm0, __shfl_xor_sync(0xffffffffu, tm0, 2));
        tm1 = fmaxf(tm1, __shfl_xor_sync(0xffffffffu, tm1, 1));
        tm1 = fmaxf(tm1, __shfl_xor_sync(0xffffffffu, tm1, 2));

        float mn0 = fmaxf(m0, tm0), mn1 = fmaxf(m1, tm1);
        float sc0 = __expf(m0 - mn0), sc1 = __expf(m1 - mn1);
        m0 = mn0; m1 = mn1;

        float ts0 = 0.f, ts1 = 0.f;
#pragma unroll
        for (int nf = 0; nf < 8; nf++) {
            s[nf][0] = __expf(s[nf][0] - m0);
            s[nf][1] = __expf(s[nf][1] - m0);
            s[nf][2] = __expf(s[nf][2] - m1);
            s[nf][3] = __expf(s[nf][3] - m1);
            ts0 += s[nf][0] + s[nf][1];
            ts1 += s[nf][2] + s[nf][3];
        }
        ts0 += __shfl_xor_sync(0xffffffffu, ts0, 1);
        ts0 += __shfl_xor_sync(0xffffffffu, ts0, 2);
        ts1 += __shfl_xor_sync(0xffffffffu, ts1, 1);
        ts1 += __shfl_xor_sync(0xffffffffu, ts1, 2);
        l0 = l0 * sc0 + ts0;
        l1 = l1 * sc1 + ts1;

#pragma unroll
        for (int nf = 0; nf < 8; nf++) {
            o[nf][0] *= sc0; o[nf][1] *= sc0;
            o[nf][2] *= sc1; o[nf][3] *= sc1;
        }

        // ---- O += P @ V (P split in-register; 3 passes) ----
#pragma unroll
        for (int j = 0; j < 4; j++) {      // key chunk of 16 = frags 2j, 2j+1
            uint32_t ah[4], al[4];
#pragma unroll
            for (int half = 0; half < 2; half++) {
                const float* p = s[2 * j + half];
#pragma unroll
                for (int rr2 = 0; rr2 < 2; rr2++) {
                    float p0 = p[rr2 * 2 + 0], p1 = p[rr2 * 2 + 1];
                    __nv_bfloat16 h0 = __float2bfloat16(p0);
                    __nv_bfloat16 h1 = __float2bfloat16(p1);
                    __nv_bfloat162 hp; hp.x = h0; hp.y = h1;
                    ah[half * 2 + rr2] = *reinterpret_cast<uint32_t*>(&hp);
                    al[half * 2 + rr2] =
                        pack_bf16(p0 - __bfloat162float(h0),
                                  p1 - __bfloat162float(h1));
                }
            }
            int vrow = j * 16 + l16;
#pragma unroll
            for (int nf = 0; nf < 8; nf++) {
                uint32_t bvh[2];
                ldsm_x2t(bvh, &sVh[vrow * APAD + nf * 8]);
                mma_16816(o[nf], ah, bvh);
                mma_16816(o[nf], al, bvh);
            }
#pragma unroll
            for (int nf = 0; nf < 8; nf++) {
                uint32_t bvl[2];
                ldsm_x2t(bvl, &sVl[vrow * APAD + nf * 8]);
                mma_16816(o[nf], ah, bvl);
            }
        }
    }

    // ---- normalize + split write ----
    float inv0 = 1.f / l0, inv1 = 1.f / l1;
    int r0 = warp * 16 + (lane >> 2);
#pragma unroll
    for (int nf = 0; nf < 8; nf++) {
        int c0 = ch + nf * 8 + (lane & 3) * 2;
#pragma unroll
        for (int hh = 0; hh < 2; hh++) {
            float v0 = o[nf][hh * 2 + 0] * (hh ? inv1 : inv0);
            float v1 = o[nf][hh * 2 + 1] * (hh ? inv1 : inv0);
            size_t idx = (rowbase + r0 + hh * 8) * D_MODEL + c0;
            __nv_bfloat16 h0 = __float2bfloat16(v0);
            __nv_bfloat16 h1 = __float2bfloat16(v1);
            __nv_bfloat162 hp; hp.x = h0; hp.y = h1;
            *reinterpret_cast<__nv_bfloat162*>(&Oh[idx]) = hp;
            __nv_bfloat162 lp;
            lp.x = __float2bfloat16(v0 - __bfloat162float(h0));
            lp.y = __float2bfloat16(v1 - __bfloat162float(h1));
            *reinterpret_cast<__nv_bfloat162*>(&Ol[idx]) = lp;
        }
    }
}

// ---------------------------------------------------------------------------
// Fused residual-add + LayerNorm (unbiased variance). Optional split output.
// ---------------------------------------------------------------------------
template <bool SPLITOUT>
__global__ __launch_bounds__(256) void add_ln_kernel(
    const float* __restrict__ A, const float* __restrict__ Bp,
    const float* __restrict__ alpha, const float* __restrict__ beta,
    float* __restrict__ out, __nv_bfloat16* __restrict__ oh,
    __nv_bfloat16* __restrict__ ol)
{
    __shared__ float buf[D_MODEL];
    __shared__ float red_s[8], red_q[8];
    __shared__ float sh_mean, sh_inv;

    const int row = blockIdx.x;
    const int tid = threadIdx.x;
    const size_t base = (size_t)row * D_MODEL;

    float s = 0.f, q = 0.f;
    for (int c = tid; c < D_MODEL; c += 256) {
        float v = A[base + c] + Bp[base + c];
        buf[c] = v;
        s += v;
        q = fmaf(v, v, q);
    }
#pragma unroll
    for (int msk = 16; msk >= 1; msk >>= 1) {
        s += __shfl_xor_sync(0xffffffffu, s, msk);
        q += __shfl_xor_sync(0xffffffffu, q, msk);
    }
    if ((tid & 31) == 0) {
        red_s[tid >> 5] = s;
        red_q[tid >> 5] = q;
    }
    __syncthreads();
    if (tid == 0) {
        float S = 0.f, Q = 0.f;
#pragma unroll
        for (int i = 0; i < 8; i++) { S += red_s[i]; Q += red_q[i]; }
        float mean = S * (1.f / (float)D_MODEL);
        float var  = fmaxf((Q - (float)D_MODEL * mean * mean) *
                           (1.f / (float)(D_MODEL - 1)), 0.f);
        sh_mean = mean;
        sh_inv  = 1.f / (sqrtf(var) + 1e-6f);
    }
    __syncthreads();
    const float mean = sh_mean, inv = sh_inv;
    for (int c = tid; c < D_MODEL; c += 256) {
        float v = fmaf(alpha[c], (buf[c] - mean) * inv, beta[c]);
        out[base + c] = v;
        if (SPLITOUT) {
            __nv_bfloat16 hv = __float2bfloat16(v);
            oh[base + c] = hv;
            ol[base + c] = __float2bfloat16(v - __bfloat162float(hv));
        }
    }
}

// ---------------------------------------------------------------------------
// Launch
// ---------------------------------------------------------------------------
extern "C" void kernel_launch(void* const* d_in, const int* in_sizes, int n_in,
                              void* d_out, int out_size)
{
    const float* x    = (const float*)d_in[0];
    const int*   mask = (const int*)  d_in[1];
    const float* w_q  = (const float*)d_in[2];
    const float* w_k  = (const float*)d_in[3];
    const float* w_v  = (const float*)d_in[4];
    const float* w_o  = (const float*)d_in[5];
    const float* W1   = (const float*)d_in[6];
    const float* b1   = (const float*)d_in[7];
    const float* W2   = (const float*)d_in[8];
    const float* b2   = (const float*)d_in[9];
    const float* a1   = (const float*)d_in[10];
    const float* be1  = (const float*)d_in[11];
    const float* a2   = (const float*)d_in[12];
    const float* be2  = (const float*)d_in[13];
    float* out = (float*)d_out;

    float *O, *X1;
    cudaGetSymbolAddress((void**)&O,  g_O);
    cudaGetSymbolAddress((void**)&X1, g_X1);

    __nv_bfloat16 *Qh, *Ql, *Kh, *Kl, *Vh, *Vl;
    __nv_bfloat16 *xh, *xl, *wqh, *wql, *wkh, *wkl, *wvh, *wvl, *woh, *wol;
    __nv_bfloat16 *W1h, *W1l, *W2h, *W2l, *aoh, *aol, *x1h, *x1l, *Hh, *Hl;
    cudaGetSymbolAddress((void**)&Qh,  g_Qh);  cudaGetSymbolAddress((void**)&Ql,  g_Ql);
    cudaGetSymbolAddress((void**)&Kh,  g_Kh);  cudaGetSymbolAddress((void**)&Kl,  g_Kl);
    cudaGetSymbolAddress((void**)&Vh,  g_Vh);  cudaGetSymbolAddress((void**)&Vl,  g_Vl);
    cudaGetSymbolAddress((void**)&xh,  g_xh);  cudaGetSymbolAddress((void**)&xl,  g_xl);
    cudaGetSymbolAddress((void**)&wqh, g_wqh); cudaGetSymbolAddress((void**)&wql, g_wql);
    cudaGetSymbolAddress((void**)&wkh, g_wkh); cudaGetSymbolAddress((void**)&wkl, g_wkl);
    cudaGetSymbolAddress((void**)&wvh, g_wvh); cudaGetSymbolAddress((void**)&wvl, g_wvl);
    cudaGetSymbolAddress((void**)&woh, g_woh); cudaGetSymbolAddress((void**)&wol, g_wol);
    cudaGetSymbolAddress((void**)&W1h, g_W1h); cudaGetSymbolAddress((void**)&W1l, g_W1l);
    cudaGetSymbolAddress((void**)&W2h, g_W2h); cudaGetSymbolAddress((void**)&W2l, g_W2l);
    cudaGetSymbolAddress((void**)&aoh, g_aoh); cudaGetSymbolAddress((void**)&aol, g_aol);
    cudaGetSymbolAddress((void**)&x1h, g_x1h); cudaGetSymbolAddress((void**)&x1l, g_x1l);
    cudaGetSymbolAddress((void**)&Hh,  g_Hh);  cudaGetSymbolAddress((void**)&Hl,  g_Hl);

    cudaFuncSetAttribute(attn_mma,
                         cudaFuncAttributeMaxDynamicSharedMemorySize,
                         ATT_SMEM_BYTES);

    const dim3 blk(256);

    // Splits of inputs/weights
    split_kernel<<<RM / 1024, blk>>>((const float4*)x,   xh,  xl,  RM / 4);
    split_kernel<<<MM / 1024, blk>>>((const float4*)w_q, wqh, wql, MM / 4);
    split_kernel<<<MM / 1024, blk>>>((const float4*)w_k, wkh, wkl, MM / 4);
    split_kernel<<<MM / 1024, blk>>>((const float4*)w_v, wvh, wvl, MM / 4);
    split_kernel<<<MM / 1024, blk>>>((const float4*)w_o, woh, wol, MM / 4);
    split_kernel<<<MF / 1024, blk>>>((const float4*)W1,  W1h, W1l, MF / 4);
    split_kernel<<<MF / 1024, blk>>>((const float4*)W2,  W2h, W2l, MF / 4);

    const dim3 gProj(D_MODEL / 128, ROWS / 128);   // (8, 32)
    const dim3 gFfn1(DFF / 128, ROWS / 128);       // (32, 32)

    // QKV projections -> bf16 split outputs
    hgemm_split3<false, false, true><<<gProj, blk>>>(
        xh, xl, wqh, wql, nullptr, nullptr, Qh, Ql, ROWS, D_MODEL, D_MODEL);
    hgemm_split3<false, false, true><<<gProj, blk>>>(
        xh, xl, wkh, wkl, nullptr, nullptr, Kh, Kl, ROWS, D_MODEL, D_MODEL);
    hgemm_split3<false, false, true><<<gProj, blk>>>(
        xh, xl, wvh, wvl, nullptr, nullptr, Vh, Vl, ROWS, D_MODEL, D_MODEL);

    // Tensor-core attention -> bf16 split output
    attn_mma<<<dim3(S_LEN / 64, HEADS, BATCH), dim3(128), ATT_SMEM_BYTES>>>(
        Qh, Ql, Kh, Kl, Vh, Vl, mask, aoh, aol);

    // Output projection -> fp32 O
    hgemm_split3<false, false, false><<<gProj, blk>>>(
        aoh, aol, woh, wol, nullptr, O, nullptr, nullptr, ROWS, D_MODEL, D_MODEL);

    // LN1: x + attn_out -> X1 (+ split)
    add_ln_kernel<true><<<ROWS, blk>>>(x, O, a1, be1, X1, x1h, x1l);

    // FFN1: relu(X1@W1 + b1) -> bf16 split H
    hgemm_split3<true, true, true><<<gFfn1, blk>>>(
        x1h, x1l, W1h, W1l, b1, nullptr, Hh, Hl, ROWS, DFF, D_MODEL);

    // FFN2: H@W2 + b2 -> fp32 O
    hgemm_split3<true, false, false><<<gProj, blk>>>(
        Hh, Hl, W2h, W2l, b2, O, nullptr, nullptr, ROWS, D_MODEL, DFF);

    // LN2: X1 + ffn_out -> out
    add_ln_kernel<false><<<ROWS, blk>>>(X1, O, a2, be2, out, nullptr, nullptr);
}

// round 8
// speedup vs baseline: 2.6334x; 1.0929x over previous
#include <cuda_runtime.h>
#include <cuda_bf16.h>
#include <math.h>
#include <stdint.h>

#define D_MODEL 1024
#define S_LEN   2048
#define BATCH   2
#define HEADS   16
#define DK      64
#define DFF     4096
#define ROWS    4096

#define RM (ROWS * D_MODEL)
#define MM (D_MODEL * D_MODEL)
#define MF (D_MODEL * DFF)
#define RF (ROWS * DFF)

__device__ float g_O [RM];
__device__ float g_X1[RM];
__device__ __nv_bfloat16 g_Qh[RM], g_Ql[RM];
__device__ __nv_bfloat16 g_Kh[RM], g_Kl[RM];
__device__ __nv_bfloat16 g_Vh[RM], g_Vl[RM];
__device__ __nv_bfloat16 g_xh [RM], g_xl [RM];
__device__ __nv_bfloat16 g_wqh[MM], g_wql[MM];
__device__ __nv_bfloat16 g_wkh[MM], g_wkl[MM];
__device__ __nv_bfloat16 g_wvh[MM], g_wvl[MM];
__device__ __nv_bfloat16 g_woh[MM], g_wol[MM];
__device__ __nv_bfloat16 g_W1h[MF], g_W1l[MF];
__device__ __nv_bfloat16 g_W2h[MF], g_W2l[MF];
__device__ __nv_bfloat16 g_aoh[RM], g_aol[RM];
__device__ __nv_bfloat16 g_x1h[RM], g_x1l[RM];
__device__ __nv_bfloat16 g_Hh [RF], g_Hl [RF];

// ---------------- helpers ----------------
__device__ __forceinline__ uint32_t pack_bf16(float a, float b)
{
    __nv_bfloat162 t; t.x = __float2bfloat16(a); t.y = __float2bfloat16(b);
    return *reinterpret_cast<uint32_t*>(&t);
}
__device__ __forceinline__ void mma_16816(float* c, const uint32_t* a, const uint32_t* b)
{
    asm volatile(
        "mma.sync.aligned.m16n8k16.row.col.f32.bf16.bf16.f32 "
        "{%0,%1,%2,%3}, {%4,%5,%6,%7}, {%8,%9}, {%0,%1,%2,%3};\n"
        : "+f"(c[0]), "+f"(c[1]), "+f"(c[2]), "+f"(c[3])
        : "r"(a[0]), "r"(a[1]), "r"(a[2]), "r"(a[3]), "r"(b[0]), "r"(b[1]));
}
__device__ __forceinline__ void cp16(void* d, const void* s)
{
    uint32_t a = (uint32_t)__cvta_generic_to_shared(d);
    asm volatile("cp.async.cg.shared.global [%0], [%1], 16;\n" :: "r"(a), "l"(s));
}
__device__ __forceinline__ void ldsm_x4(uint32_t* r, const void* p)
{
    uint32_t a = (uint32_t)__cvta_generic_to_shared(p);
    asm volatile("ldmatrix.sync.aligned.m8n8.x4.shared.b16 {%0,%1,%2,%3}, [%4];\n"
                 : "=r"(r[0]), "=r"(r[1]), "=r"(r[2]), "=r"(r[3]) : "r"(a));
}
__device__ __forceinline__ void ldsm_x2(uint32_t* r, const void* p)
{
    uint32_t a = (uint32_t)__cvta_generic_to_shared(p);
    asm volatile("ldmatrix.sync.aligned.m8n8.x2.shared.b16 {%0,%1}, [%2];\n"
                 : "=r"(r[0]), "=r"(r[1]) : "r"(a));
}
__device__ __forceinline__ void ldsm_x2t(uint32_t* r, const void* p)
{
    uint32_t a = (uint32_t)__cvta_generic_to_shared(p);
    asm volatile("ldmatrix.sync.aligned.m8n8.x2.trans.shared.b16 {%0,%1}, [%2];\n"
                 : "=r"(r[0]), "=r"(r[1]) : "r"(a));
}

// ---------------- split ----------------
__global__ __launch_bounds__(256) void split_kernel(
    const float4* __restrict__ x, __nv_bfloat16* __restrict__ hi,
    __nv_bfloat16* __restrict__ lo, int n4)
{
    int i = blockIdx.x * 256 + threadIdx.x;
    if (i >= n4) return;
    float4 v = x[i];
    __nv_bfloat16 h0 = __float2bfloat16(v.x), h1 = __float2bfloat16(v.y);
    __nv_bfloat16 h2 = __float2bfloat16(v.z), h3 = __float2bfloat16(v.w);
    __nv_bfloat162 a; a.x = h0; a.y = h1;
    __nv_bfloat162 b; b.x = h2; b.y = h3;
    *reinterpret_cast<__nv_bfloat162*>(&hi[i * 4])     = a;
    *reinterpret_cast<__nv_bfloat162*>(&hi[i * 4 + 2]) = b;
    __nv_bfloat162 c, d;
    c.x = __float2bfloat16(v.x - __bfloat162float(h0));
    c.y = __float2bfloat16(v.y - __bfloat162float(h1));
    d.x = __float2bfloat16(v.z - __bfloat162float(h2));
    d.y = __float2bfloat16(v.w - __bfloat162float(h3));
    *reinterpret_cast<__nv_bfloat162*>(&lo[i * 4])     = c;
    *reinterpret_cast<__nv_bfloat162*>(&lo[i * 4 + 2]) = d;
}

// ---------------------------------------------------------------------------
// Fused split-3 bf16 GEMM: tile 128x256, BK=32, 256 threads (8 warps, 64x64
// warp tiles). Loads Ah,Al,Bh,Bl once per K-chunk; all 3 products per chunk.
// A: [M,K] (K-major), B: [K,N] (native weight layout).
// ---------------------------------------------------------------------------
#define GA_ROW 40                      // halves per A smem row (80 B)
#define GB_ROW 264                     // halves per B smem row (528 B)
#define A_BYTES (128 * GA_ROW * 2)     // 10240
#define B_BYTES (32 * GB_ROW * 2)      // 16896
#define GSMEM_TOTAL (4 * A_BYTES + 4 * B_BYTES)   // 108544

template <bool BIAS, bool RELU, bool SPLIT>
__global__ __launch_bounds__(256) void hgemm_fused(
    const __nv_bfloat16* __restrict__ Ah_, const __nv_bfloat16* __restrict__ Al_,
    const __nv_bfloat16* __restrict__ Bh_, const __nv_bfloat16* __restrict__ Bl_,
    const float* __restrict__ bias, float* __restrict__ C,
    __nv_bfloat16* __restrict__ Ch, __nv_bfloat16* __restrict__ Cl,
    int M, int N, int K)
{
    extern __shared__ __align__(16) char gsm[];
    // layout: Ah[s=0,1], Al[s=0,1], Bh[s=0,1], Bl[s=0,1]
    auto As = [&](int hl, int s) {
        return (__nv_bfloat16*)(gsm + (hl * 2 + s) * A_BYTES);
    };
    auto Bs = [&](int hl, int s) {
        return (__nv_bfloat16*)(gsm + 4 * A_BYTES + (hl * 2 + s) * B_BYTES);
    };

    const int tid  = threadIdx.x;
    const int lane = tid & 31;
    const int warp = tid >> 5;
    const int wm   = warp & 1;         // 0..1 -> 64-row slab
    const int wn   = warp >> 1;        // 0..3 -> 64-col slab
    const int rowBase = blockIdx.y * 128;
    const int colBase = blockIdx.x * 256;

    const int nc = K / 32;

    float acc[4][8][4];
#pragma unroll
    for (int i = 0; i < 4; i++)
#pragma unroll
        for (int j = 0; j < 8; j++)
#pragma unroll
            for (int k = 0; k < 4; k++) acc[i][j][k] = 0.f;

    auto issue = [&](int c, int s) {
        int k0 = c * 32;
        // A tiles: 128 rows x 32 halves, 2 cp16 per thread per array
#pragma unroll
        for (int i = 0; i < 2; i++) {
            int t = tid * 2 + i;            // 0..511
            int r = t >> 2, c8 = (t & 3) * 8;
            const size_t g = (size_t)(rowBase + r) * K + k0 + c8;
            cp16(As(0, s) + r * GA_ROW + c8, Ah_ + g);
            cp16(As(1, s) + r * GA_ROW + c8, Al_ + g);
        }
        // B tiles: 32 rows x 256 halves, 4 cp16 per thread per array
#pragma unroll
        for (int i = 0; i < 4; i++) {
            int t = tid + i * 256;          // 0..1023
            int r = t >> 5, c8 = (t & 31) * 8;
            const size_t g = (size_t)(k0 + r) * N + colBase + c8;
            cp16(Bs(0, s) + r * GB_ROW + c8, Bh_ + g);
            cp16(Bs(1, s) + r * GB_ROW + c8, Bl_ + g);
        }
        asm volatile("cp.async.commit_group;\n" ::: "memory");
    };

    issue(0, 0);
    for (int c = 0; c < nc; c++) {
        asm volatile("cp.async.wait_group 0;\n" ::: "memory");
        __syncthreads();
        const int s = c & 1;
        if (c + 1 < nc) issue(c + 1, s ^ 1);

#pragma unroll
        for (int ks = 0; ks < 32; ks += 16) {
            uint32_t ahf[4][4], alf[4][4];
#pragma unroll
            for (int fm = 0; fm < 4; fm++) {
                int row = wm * 64 + fm * 16 + (lane & 15);
                int col = ks + ((lane >> 4) << 3);
                ldsm_x4(ahf[fm], As(0, s) + row * GA_ROW + col);
                ldsm_x4(alf[fm], As(1, s) + row * GA_ROW + col);
            }
            const int brow = ks + (lane & 15);
#pragma unroll
            for (int fn = 0; fn < 8; fn++) {
                const int bcol = wn * 64 + fn * 8;
                uint32_t bh[2];
                ldsm_x2t(bh, Bs(0, s) + brow * GB_ROW + bcol);
#pragma unroll
                for (int fm = 0; fm < 4; fm++) mma_16816(acc[fm][fn], ahf[fm], bh);
#pragma unroll
                for (int fm = 0; fm < 4; fm++) mma_16816(acc[fm][fn], alf[fm], bh);
                uint32_t bl[2];
                ldsm_x2t(bl, Bs(1, s) + brow * GB_ROW + bcol);
#pragma unroll
                for (int fm = 0; fm < 4; fm++) mma_16816(acc[fm][fn], ahf[fm], bl);
            }
        }
        __syncthreads();
    }

    // epilogue
#pragma unroll
    for (int fm = 0; fm < 4; fm++) {
#pragma unroll
        for (int fn = 0; fn < 8; fn++) {
            int r0 = rowBase + wm * 64 + fm * 16 + (lane >> 2);
            int c0 = colBase + wn * 64 + fn * 8 + (lane & 3) * 2;
            float bx = 0.f, by = 0.f;
            if (BIAS) { bx = bias[c0]; by = bias[c0 + 1]; }
#pragma unroll
            for (int hh = 0; hh < 2; hh++) {
                int r = r0 + hh * 8;
                float v0 = acc[fm][fn][hh * 2 + 0] + bx;
                float v1 = acc[fm][fn][hh * 2 + 1] + by;
                if (RELU) { v0 = fmaxf(v0, 0.f); v1 = fmaxf(v1, 0.f); }
                size_t idx = (size_t)r * N + c0;
                if (SPLIT) {
                    __nv_bfloat16 h0 = __float2bfloat16(v0);
                    __nv_bfloat16 h1 = __float2bfloat16(v1);
                    __nv_bfloat162 hp; hp.x = h0; hp.y = h1;
                    *reinterpret_cast<__nv_bfloat162*>(&Ch[idx]) = hp;
                    __nv_bfloat162 lp;
                    lp.x = __float2bfloat16(v0 - __bfloat162float(h0));
                    lp.y = __float2bfloat16(v1 - __bfloat162float(h1));
                    *reinterpret_cast<__nv_bfloat162*>(&Cl[idx]) = lp;
                } else {
                    *reinterpret_cast<float2*>(&C[idx]) = make_float2(v0, v1);
                }
            }
        }
    }
}

// ---------------- attention (mma.sync, split-3) ----------------
#define APAD 72
#define ATILE (64 * APAD)
#define ATT_SMEM_BYTES (6 * ATILE * 2 + 64 * 4)

__global__ __launch_bounds__(128) void attn_mma(
    const __nv_bfloat16* __restrict__ Qh, const __nv_bfloat16* __restrict__ Ql,
    const __nv_bfloat16* __restrict__ Kh, const __nv_bfloat16* __restrict__ Kl,
    const __nv_bfloat16* __restrict__ Vh, const __nv_bfloat16* __restrict__ Vl,
    const int* __restrict__ mask,
    __nv_bfloat16* __restrict__ Oh, __nv_bfloat16* __restrict__ Ol)
{
    extern __shared__ __align__(16) __nv_bfloat16 smb[];
    __nv_bfloat16* sQh = smb;
    __nv_bfloat16* sQl = smb + ATILE;
    __nv_bfloat16* sKh = smb + 2 * ATILE;
    __nv_bfloat16* sKl = smb + 3 * ATILE;
    __nv_bfloat16* sVh = smb + 4 * ATILE;
    __nv_bfloat16* sVl = smb + 5 * ATILE;
    int* Ms = (int*)(smb + 6 * ATILE);

    const int qt = blockIdx.x, h = blockIdx.y, b = blockIdx.z;
    const int tid = threadIdx.x, lane = tid & 31, warp = tid >> 5, l16 = lane & 15;
    const size_t rowbase = (size_t)b * S_LEN + qt * 64;
    const int ch = h * DK;

    for (int i = tid; i < 512; i += 128) {
        int r = i >> 3, c8 = (i & 7) * 8;
        size_t g = (rowbase + r) * D_MODEL + ch + c8;
        cp16(&sQh[r * APAD + c8], Qh + g);
        cp16(&sQl[r * APAD + c8], Ql + g);
    }
    asm volatile("cp.async.commit_group;\n" ::: "memory");
    asm volatile("cp.async.wait_group 0;\n" ::: "memory");
    __syncthreads();

    uint32_t qfh[4][4], qfl[4][4];
#pragma unroll
    for (int kc = 0; kc < 4; kc++) {
        int row = warp * 16 + l16, col = kc * 16 + (lane >> 4) * 8;
        ldsm_x4(qfh[kc], &sQh[row * APAD + col]);
        ldsm_x4(qfl[kc], &sQl[row * APAD + col]);
    }

    float m0 = -1e30f, m1 = -1e30f, l0 = 0.f, l1 = 0.f;
    float o[8][4];
#pragma unroll
    for (int nf = 0; nf < 8; nf++)
#pragma unroll
        for (int j = 0; j < 4; j++) o[nf][j] = 0.f;

    for (int kt = 0; kt < S_LEN / 64; kt++) {
        __syncthreads();
        for (int i = tid; i < 512; i += 128) {
            int r = i >> 3, c8 = (i & 7) * 8;
            size_t g = ((size_t)b * S_LEN + kt * 64 + r) * D_MODEL + ch + c8;
            int so = r * APAD + c8;
            cp16(&sKh[so], Kh + g);
            cp16(&sKl[so], Kl + g);
            cp16(&sVh[so], Vh + g);
            cp16(&sVl[so], Vl + g);
        }
        if (tid < 64) Ms[tid] = mask[(size_t)b * S_LEN + kt * 64 + tid];
        asm volatile("cp.async.commit_group;\n" ::: "memory");
        asm volatile("cp.async.wait_group 0;\n" ::: "memory");
        __syncthreads();

        float s[8][4];
#pragma unroll
        for (int nf = 0; nf < 8; nf++)
#pragma unroll
            for (int j = 0; j < 4; j++) s[nf][j] = 0.f;

#pragma unroll
        for (int kc = 0; kc < 4; kc++) {
            int rr = (l16 & 7), cc = kc * 16 + (l16 >> 3) * 8;
#pragma unroll
            for (int nf = 0; nf < 8; nf++) {
                uint32_t bh[2];
                ldsm_x2(bh, &sKh[(nf * 8 + rr) * APAD + cc]);
                mma_16816(s[nf], qfh[kc], bh);
                mma_16816(s[nf], qfl[kc], bh);
            }
#pragma unroll
            for (int nf = 0; nf < 8; nf++) {
                uint32_t bl[2];
                ldsm_x2(bl, &sKl[(nf * 8 + rr) * APAD + cc]);
                mma_16816(s[nf], qfh[kc], bl);
            }
        }

#pragma unroll
        for (int nf = 0; nf < 8; nf++) {
            int c0 = nf * 8 + (lane & 3) * 2;
            bool z0 = (Ms[c0] == 0), z1 = (Ms[c0 + 1] == 0);
            s[nf][0] = z0 ? -1e9f : s[nf][0] * 0.125f;
            s[nf][1] = z1 ? -1e9f : s[nf][1] * 0.125f;
            s[nf][2] = z0 ? -1e9f : s[nf][2] * 0.125f;
            s[nf][3] = z1 ? -1e9f : s[nf][3] * 0.125f;
        }

        float tm0 = -1e30f, tm1 = -1e30f;
#pragma unroll
        for (int nf = 0; nf < 8; nf++) {
            tm0 = fmaxf(tm0, fmaxf(s[nf][0], s[nf][1]));
            tm1 = fmaxf(tm1, fmaxf(s[nf][2], s[nf][3]));
        }
        tm0 = fmaxf(tm0, __shfl_xor_sync(0xffffffffu, tm0, 1));
        tm0 = fmaxf(tm0, __shfl_xor_sync(0xffffffffu, tm0, 2));
        tm1 = fmaxf(tm1, __shfl_xor_sync(0xffffffffu, tm1, 1));
        tm1 = fmaxf(tm1, __shfl_xor_sync(0xffffffffu, tm1, 2));

        float mn0 = fmaxf(m0, tm0), mn1 = fmaxf(m1, tm1);
        float sc0 = __expf(m0 - mn0), sc1 = __expf(m1 - mn1);
        m0 = mn0; m1 = mn1;

        float ts0 = 0.f, ts1 = 0.f;
#pragma unroll
        for (int nf = 0; nf < 8; nf++) {
            s[nf][0] = __expf(s[nf][0] - m0);
            s[nf][1] = __expf(s[nf][1] - m0);
            s[nf][2] = __expf(s[nf][2] - m1);
            s[nf][3] = __expf(s[nf][3] - m1);
            ts0 += s[nf][0] + s[nf][1];
            ts1 += s[nf][2] + s[nf][3];
        }
        ts0 += __shfl_xor_sync(0xffffffffu, ts0, 1);
        ts0 += __shfl_xor_sync(0xffffffffu, ts0, 2);
        ts1 += __shfl_xor_sync(0xffffffffu, ts1, 1);
        ts1 += __shfl_xor_sync(0xffffffffu, ts1, 2);
        l0 = l0 * sc0 + ts0;
        l1 = l1 * sc1 + ts1;

#pragma unroll
        for (int nf = 0; nf < 8; nf++) {
            o[nf][0] *= sc0; o[nf][1] *= sc0;
            o[nf][2] *= sc1; o[nf][3] *= sc1;
        }

#pragma unroll
        for (int j = 0; j < 4; j++) {
            uint32_t ah[4], al[4];
#pragma unroll
            for (int half = 0; half < 2; half++) {
                const float* p = s[2 * j + half];
#pragma unroll
                for (int rr2 = 0; rr2 < 2; rr2++) {
                    float p0 = p[rr2 * 2 + 0], p1 = p[rr2 * 2 + 1];
                    __nv_bfloat16 h0 = __float2bfloat16(p0), h1 = __float2bfloat16(p1);
                    __nv_bfloat162 hp; hp.x = h0; hp.y = h1;
                    ah[half * 2 + rr2] = *reinterpret_cast<uint32_t*>(&hp);
                    al[half * 2 + rr2] = pack_bf16(p0 - __bfloat162float(h0),
                                                   p1 - __bfloat162float(h1));
                }
            }
            int vrow = j * 16 + l16;
#pragma unroll
            for (int nf = 0; nf < 8; nf++) {
                uint32_t bvh[2];
                ldsm_x2t(bvh, &sVh[vrow * APAD + nf * 8]);
                mma_16816(o[nf], ah, bvh);
                mma_16816(o[nf], al, bvh);
            }
#pragma unroll
            for (int nf = 0; nf < 8; nf++) {
                uint32_t bvl[2];
                ldsm_x2t(bvl, &sVl[vrow * APAD + nf * 8]);
                mma_16816(o[nf], ah, bvl);
            }
        }
    }

    float inv0 = 1.f / l0, inv1 = 1.f / l1;
    int r0 = warp * 16 + (lane >> 2);
#pragma unroll
    for (int nf = 0; nf < 8; nf++) {
        int c0 = ch + nf * 8 + (lane & 3) * 2;
#pragma unroll
        for (int hh = 0; hh < 2; hh++) {
            float v0 = o[nf][hh * 2 + 0] * (hh ? inv1 : inv0);
            float v1 = o[nf][hh * 2 + 1] * (hh ? inv1 : inv0);
            size_t idx = (rowbase + r0 + hh * 8) * D_MODEL + c0;
            __nv_bfloat16 h0 = __float2bfloat16(v0), h1 = __float2bfloat16(v1);
            __nv_bfloat162 hp; hp.x = h0; hp.y = h1;
            *reinterpret_cast<__nv_bfloat162*>(&Oh[idx]) = hp;
            __nv_bfloat162 lp;
            lp.x = __float2bfloat16(v0 - __bfloat162float(h0));
            lp.y = __float2bfloat16(v1 - __bfloat162float(h1));
            *reinterpret_cast<__nv_bfloat162*>(&Ol[idx]) = lp;
        }
    }
}

// ---------------- residual + LayerNorm ----------------
template <bool SPLITOUT>
__global__ __launch_bounds__(256) void add_ln_kernel(
    const float* __restrict__ A, const float* __restrict__ Bp,
    const float* __restrict__ alpha, const float* __restrict__ beta,
    float* __restrict__ out, __nv_bfloat16* __restrict__ oh,
    __nv_bfloat16* __restrict__ ol)
{
    __shared__ float buf[D_MODEL];
    __shared__ float red_s[8], red_q[8];
    __shared__ float sh_mean, sh_inv;
    const int row = blockIdx.x, tid = threadIdx.x;
    const size_t base = (size_t)row * D_MODEL;

    float s = 0.f, q = 0.f;
    for (int c = tid; c < D_MODEL; c += 256) {
        float v = A[base + c] + Bp[base + c];
        buf[c] = v; s += v; q = fmaf(v, v, q);
    }
#pragma unroll
    for (int msk = 16; msk >= 1; msk >>= 1) {
        s += __shfl_xor_sync(0xffffffffu, s, msk);
        q += __shfl_xor_sync(0xffffffffu, q, msk);
    }
    if ((tid & 31) == 0) { red_s[tid >> 5] = s; red_q[tid >> 5] = q; }
    __syncthreads();
    if (tid == 0) {
        float S = 0.f, Q = 0.f;
#pragma unroll
        for (int i = 0; i < 8; i++) { S += red_s[i]; Q += red_q[i]; }
        float mean = S * (1.f / (float)D_MODEL);
        float var = fmaxf((Q - (float)D_MODEL * mean * mean) *
                          (1.f / (float)(D_MODEL - 1)), 0.f);
        sh_mean = mean;
        sh_inv = 1.f / (sqrtf(var) + 1e-6f);
    }
    __syncthreads();
    const float mean = sh_mean, inv = sh_inv;
    for (int c = tid; c < D_MODEL; c += 256) {
        float v = fmaf(alpha[c], (buf[c] - mean) * inv, beta[c]);
        out[base + c] = v;
        if (SPLITOUT) {
            __nv_bfloat16 hv = __float2bfloat16(v);
            oh[base + c] = hv;
            ol[base + c] = __float2bfloat16(v - __bfloat162float(hv));
        }
    }
}

// ---------------- launch ----------------
extern "C" void kernel_launch(void* const* d_in, const int* in_sizes, int n_in,
                              void* d_out, int out_size)
{
    const float* x   = (const float*)d_in[0];
    const int* mask  = (const int*)d_in[1];
    const float* w_q = (const float*)d_in[2];
    const float* w_k = (const float*)d_in[3];
    const float* w_v = (const float*)d_in[4];
    const float* w_o = (const float*)d_in[5];
    const float* W1  = (const float*)d_in[6];
    const float* b1  = (const float*)d_in[7];
    const float* W2  = (const float*)d_in[8];
    const float* b2  = (const float*)d_in[9];
    const float* a1  = (const float*)d_in[10];
    const float* be1 = (const float*)d_in[11];
    const float* a2  = (const float*)d_in[12];
    const float* be2 = (const float*)d_in[13];
    float* out = (float*)d_out;

    float *O, *X1;
    cudaGetSymbolAddress((void**)&O, g_O);
    cudaGetSymbolAddress((void**)&X1, g_X1);
    __nv_bfloat16 *Qh, *Ql, *Kh, *Kl, *Vh, *Vl;
    __nv_bfloat16 *xh, *xl, *wqh, *wql, *wkh, *wkl, *wvh, *wvl, *woh, *wol;
    __nv_bfloat16 *W1h, *W1l, *W2h, *W2l, *aoh, *aol, *x1h, *x1l, *Hh, *Hl;
    cudaGetSymbolAddress((void**)&Qh, g_Qh);   cudaGetSymbolAddress((void**)&Ql, g_Ql);
    cudaGetSymbolAddress((void**)&Kh, g_Kh);   cudaGetSymbolAddress((void**)&Kl, g_Kl);
    cudaGetSymbolAddress((void**)&Vh, g_Vh);   cudaGetSymbolAddress((void**)&Vl, g_Vl);
    cudaGetSymbolAddress((void**)&xh, g_xh);   cudaGetSymbolAddress((void**)&xl, g_xl);
    cudaGetSymbolAddress((void**)&wqh, g_wqh); cudaGetSymbolAddress((void**)&wql, g_wql);
    cudaGetSymbolAddress((void**)&wkh, g_wkh); cudaGetSymbolAddress((void**)&wkl, g_wkl);
    cudaGetSymbolAddress((void**)&wvh, g_wvh); cudaGetSymbolAddress((void**)&wvl, g_wvl);
    cudaGetSymbolAddress((void**)&woh, g_woh); cudaGetSymbolAddress((void**)&wol, g_wol);
    cudaGetSymbolAddress((void**)&W1h, g_W1h); cudaGetSymbolAddress((void**)&W1l, g_W1l);
    cudaGetSymbolAddress((void**)&W2h, g_W2h); cudaGetSymbolAddress((void**)&W2l, g_W2l);
    cudaGetSymbolAddress((void**)&aoh, g_aoh); cudaGetSymbolAddress((void**)&aol, g_aol);
    cudaGetSymbolAddress((void**)&x1h, g_x1h); cudaGetSymbolAddress((void**)&x1l, g_x1l);
    cudaGetSymbolAddress((void**)&Hh, g_Hh);   cudaGetSymbolAddress((void**)&Hl, g_Hl);

    cudaFuncSetAttribute(attn_mma, cudaFuncAttributeMaxDynamicSharedMemorySize,
                         ATT_SMEM_BYTES);
    cudaFuncSetAttribute(hgemm_fused<false, false, true>,
                         cudaFuncAttributeMaxDynamicSharedMemorySize, GSMEM_TOTAL);
    cudaFuncSetAttribute(hgemm_fused<false, false, false>,
                         cudaFuncAttributeMaxDynamicSharedMemorySize, GSMEM_TOTAL);
    cudaFuncSetAttribute(hgemm_fused<true, true, true>,
                         cudaFuncAttributeMaxDynamicSharedMemorySize, GSMEM_TOTAL);
    cudaFuncSetAttribute(hgemm_fused<true, false, false>,
                         cudaFuncAttributeMaxDynamicSharedMemorySize, GSMEM_TOTAL);

    const dim3 blk(256);
    const dim3 gP(D_MODEL / 256, ROWS / 128);   // (4, 32)
    const dim3 gF(DFF / 256, ROWS / 128);       // (16, 32)

    // 0-3: splits needed by QKV; 4-6: QKV GEMMs (ncu -s 5 lands on K-proj GEMM)
    split_kernel<<<RM / 1024, blk>>>((const float4*)x, xh, xl, RM / 4);
    split_kernel<<<MM / 1024, blk>>>((const float4*)w_q, wqh, wql, MM / 4);
    split_kernel<<<MM / 1024, blk>>>((const float4*)w_k, wkh, wkl, MM / 4);
    split_kernel<<<MM / 1024, blk>>>((const float4*)w_v, wvh, wvl, MM / 4);

    hgemm_fused<false, false, true><<<gP, blk, GSMEM_TOTAL>>>(
        xh, xl, wqh, wql, nullptr, nullptr, Qh, Ql, ROWS, D_MODEL, D_MODEL);
    hgemm_fused<false, false, true><<<gP, blk, GSMEM_TOTAL>>>(
        xh, xl, wkh, wkl, nullptr, nullptr, Kh, Kl, ROWS, D_MODEL, D_MODEL);
    hgemm_fused<false, false, true><<<gP, blk, GSMEM_TOTAL>>>(
        xh, xl, wvh, wvl, nullptr, nullptr, Vh, Vl, ROWS, D_MODEL, D_MODEL);

    split_kernel<<<MM / 1024, blk>>>((const float4*)w_o, woh, wol, MM / 4);
    split_kernel<<<MF / 1024, blk>>>((const float4*)W1, W1h, W1l, MF / 4);
    split_kernel<<<MF / 1024, blk>>>((const float4*)W2, W2h, W2l, MF / 4);

    attn_mma<<<dim3(S_LEN / 64, HEADS, BATCH), 128, ATT_SMEM_BYTES>>>(
        Qh, Ql, Kh, Kl, Vh, Vl, mask, aoh, aol);

    hgemm_fused<false, false, false><<<gP, blk, GSMEM_TOTAL>>>(
        aoh, aol, woh, wol, nullptr, O, nullptr, nullptr, ROWS, D_MODEL, D_MODEL);

    add_ln_kernel<true><<<ROWS, blk>>>(x, O, a1, be1, X1, x1h, x1l);

    hgemm_fused<true, true, true><<<gF, blk, GSMEM_TOTAL>>>(
        x1h, x1l, W1h, W1l, b1, nullptr, Hh, Hl, ROWS, DFF, D_MODEL);

    hgemm_fused<true, false, false><<<gP, blk, GSMEM_TOTAL>>>(
        Hh, Hl, W2h, W2l, b2, O, nullptr, nullptr, ROWS, D_MODEL, DFF);

    add_ln_kernel<false><<<ROWS, blk>>>(X1, O, a2, be2, out, nullptr, nullptr);
}